// round 6
// baseline (speedup 1.0000x reference)
#include <cuda_runtime.h>
#include <math.h>

#define BB      4
#define NSEQ    512
#define DMODEL  512
#define NH      8
#define DK      64
#define TOK     (BB*NSEQ)      // 2048
#define DINNER  2048
#define LN_EPS  1e-6f
#define INV_T   0.125f         // 1/sqrt(64)

// ---------------- scratch (no allocation allowed -> __device__ globals) ----
__device__ float g_q[BB*NH*NSEQ*DK];        // [b,h,n,d]
__device__ float g_k[BB*NH*NSEQ*DK];
__device__ float g_v[BB*NH*NSEQ*DK];
__device__ float g_Mmat[DK*4];              // combined rp matrix  M[d][p]
__device__ float g_cvec[DK];                // combined rp bias    c[d]
__device__ float g_heads[TOK*DMODEL];       // [b,n, h*dv]  (attn @ V, transposed)
__device__ float g_tmp1[TOK*DMODEL];        // fc + residual (pre-LN1)
__device__ float g_ln1[TOK*DMODEL];         // LN1 output (FFN residual)
__device__ float g_ffh[TOK*DINNER];         // relu(FFN hidden)
__device__ float g_tmp2[TOK*DMODEL];        // FFN out + residual (pre-LN2)

// ---------------- warp reduce helpers --------------------------------------
__device__ __forceinline__ float warp_sum(float v) {
    #pragma unroll
    for (int o = 16; o; o >>= 1) v += __shfl_xor_sync(0xffffffffu, v, o);
    return v;
}
__device__ __forceinline__ float warp_max(float v) {
    #pragma unroll
    for (int o = 16; o; o >>= 1) v = fmaxf(v, __shfl_xor_sync(0xffffffffu, v, o));
    return v;
}

// ---------------- collapse rel-pos MLP: M = W2@W1, c = W2@b1 + b2 ----------
__global__ void rp_combine_kernel(const float* __restrict__ w1, const float* __restrict__ b1,
                                  const float* __restrict__ w2, const float* __restrict__ b2) {
    int d = threadIdx.x;
    if (d >= DK) return;
    float m0 = 0.f, m1 = 0.f, m2 = 0.f, m3 = 0.f, cc = 0.f;
    for (int k = 0; k < DK; k++) {
        float w = w2[d*DK + k];
        m0 = fmaf(w, w1[k*4+0], m0);
        m1 = fmaf(w, w1[k*4+1], m1);
        m2 = fmaf(w, w1[k*4+2], m2);
        m3 = fmaf(w, w1[k*4+3], m3);
        cc = fmaf(w, b1[k],      cc);
    }
    g_Mmat[d*4+0] = m0; g_Mmat[d*4+1] = m1;
    g_Mmat[d*4+2] = m2; g_Mmat[d*4+3] = m3;
    g_cvec[d] = cc + b2[d];
}

// ---------------- generic C = A @ B^T (+bias, +resid, relu, qkv-remap) -----
// A: [M,K] row-major, B: [N,K] row-major. Tile 64x64, BK=16, 256 thr, 4x4/thr.
template<bool BIAS, bool RELU, bool RESID, bool QKVMAP>
__global__ __launch_bounds__(256)
void gemm_nt_kernel(const float* __restrict__ A, const float* __restrict__ B,
                    const float* __restrict__ bias, const float* __restrict__ resid,
                    float* __restrict__ C, int M, int N, int K)
{
    __shared__ float As[16][64];   // k-major
    __shared__ float Bs[16][64];
    int tid  = threadIdx.x;
    int tx   = tid & 15, ty = tid >> 4;
    int row0 = blockIdx.y << 6, col0 = blockIdx.x << 6;
    int lr   = tid >> 2;           // 0..63
    int lk   = (tid & 3) << 2;     // 0,4,8,12
    const float* Ald = A + (size_t)(row0 + lr) * K + lk;
    const float* Bld = B + (size_t)(col0 + lr) * K + lk;

    float acc[4][4] = {};
    for (int k0 = 0; k0 < K; k0 += 16) {
        float4 av = *(const float4*)(Ald + k0);
        float4 bv = *(const float4*)(Bld + k0);
        As[lk+0][lr] = av.x; As[lk+1][lr] = av.y; As[lk+2][lr] = av.z; As[lk+3][lr] = av.w;
        Bs[lk+0][lr] = bv.x; Bs[lk+1][lr] = bv.y; Bs[lk+2][lr] = bv.z; Bs[lk+3][lr] = bv.w;
        __syncthreads();
        #pragma unroll
        for (int kk = 0; kk < 16; kk++) {
            float4 a = *(const float4*)&As[kk][ty << 2];
            float4 b = *(const float4*)&Bs[kk][tx << 2];
            acc[0][0] = fmaf(a.x, b.x, acc[0][0]); acc[0][1] = fmaf(a.x, b.y, acc[0][1]);
            acc[0][2] = fmaf(a.x, b.z, acc[0][2]); acc[0][3] = fmaf(a.x, b.w, acc[0][3]);
            acc[1][0] = fmaf(a.y, b.x, acc[1][0]); acc[1][1] = fmaf(a.y, b.y, acc[1][1]);
            acc[1][2] = fmaf(a.y, b.z, acc[1][2]); acc[1][3] = fmaf(a.y, b.w, acc[1][3]);
            acc[2][0] = fmaf(a.z, b.x, acc[2][0]); acc[2][1] = fmaf(a.z, b.y, acc[2][1]);
            acc[2][2] = fmaf(a.z, b.z, acc[2][2]); acc[2][3] = fmaf(a.z, b.w, acc[2][3]);
            acc[3][0] = fmaf(a.w, b.x, acc[3][0]); acc[3][1] = fmaf(a.w, b.y, acc[3][1]);
            acc[3][2] = fmaf(a.w, b.z, acc[3][2]); acc[3][3] = fmaf(a.w, b.w, acc[3][3]);
        }
        __syncthreads();
    }
    #pragma unroll
    for (int ii = 0; ii < 4; ii++) {
        int r = row0 + (ty << 2) + ii;
        #pragma unroll
        for (int jj = 0; jj < 4; jj++) {
            int c = col0 + (tx << 2) + jj;
            float v = acc[ii][jj];
            if (BIAS)  v += bias[c];
            if (RESID) v += resid[(size_t)r * N + c];
            if (RELU)  v = fmaxf(v, 0.0f);
            if (QKVMAP) {
                // r = token (b*512+n), c = h*64+d  ->  [b,h,n,d]
                int bb = r >> 9, nn = r & (NSEQ-1), hh = c >> 6, dd = c & (DK-1);
                C[(((size_t)(bb*NH + hh) * NSEQ) + nn) * DK + dd] = v;
            } else {
                C[(size_t)r * N + c] = v;
            }
        }
    }
}

// ---------------- fused relative attention scores ---------------------------
// attn_raw[b,h,j,i] = (1/T) * sum_d q[b,h,i,d]*k[b,h,j,d]*(c[d] + pos[b,j,i,:]·M[d,:])
// Block: 32x32 (j,i) tile, all 8 heads; 256 threads, 2x2 pairs per thread.
__global__ __launch_bounds__(256)
void scores_kernel(const float* __restrict__ pos, float* __restrict__ attn)
{
    __shared__ float Qs[16][256];  // [dd][h*32 + i_local]
    __shared__ float Ks[16][256];  // [dd][h*32 + j_local]
    __shared__ float Ms[DK*4];
    __shared__ float Cs[DK];

    int tid = threadIdx.x;
    int b   = blockIdx.z;
    int i0  = blockIdx.x << 5, j0 = blockIdx.y << 5;
    int tx  = tid & 15, ty = tid >> 4;
    int il  = tx << 1, jl = ty << 1;

    Ms[tid] = g_Mmat[tid];
    if (tid < DK) Cs[tid] = g_cvec[tid];

    float4 pr[2][2];
    #pragma unroll
    for (int jj = 0; jj < 2; jj++)
        #pragma unroll
        for (int ii = 0; ii < 2; ii++)
            pr[jj][ii] = *(const float4*)(pos +
                (((size_t)(b*NSEQ + j0 + jl + jj) * NSEQ) + (i0 + il + ii)) * 4);

    float acc[2][2][NH];
    #pragma unroll
    for (int jj = 0; jj < 2; jj++)
        #pragma unroll
        for (int ii = 0; ii < 2; ii++)
            #pragma unroll
            for (int h = 0; h < NH; h++) acc[jj][ii][h] = 0.f;

    int fh = tid >> 5, fi = tid & 31;
    const float* qb = g_q + (((size_t)(b*NH + fh) * NSEQ) + i0 + fi) * DK;
    const float* kb = g_k + (((size_t)(b*NH + fh) * NSEQ) + j0 + fi) * DK;
    int base = fh * 32 + fi;

    for (int dc = 0; dc < DK; dc += 16) {
        __syncthreads();
        #pragma unroll
        for (int c4 = 0; c4 < 4; c4++) {
            float4 qv = *(const float4*)(qb + dc + c4*4);
            float4 kv = *(const float4*)(kb + dc + c4*4);
            Qs[c4*4+0][base] = qv.x; Qs[c4*4+1][base] = qv.y;
            Qs[c4*4+2][base] = qv.z; Qs[c4*4+3][base] = qv.w;
            Ks[c4*4+0][base] = kv.x; Ks[c4*4+1][base] = kv.y;
            Ks[c4*4+2][base] = kv.z; Ks[c4*4+3][base] = kv.w;
        }
        __syncthreads();
        #pragma unroll
        for (int dd = 0; dd < 16; dd++) {
            int d = dc + dd;
            float m0 = Ms[d*4+0], m1 = Ms[d*4+1], m2 = Ms[d*4+2], m3 = Ms[d*4+3];
            float cc = Cs[d];
            float ak[2][2];
            #pragma unroll
            for (int jj = 0; jj < 2; jj++)
                #pragma unroll
                for (int ii = 0; ii < 2; ii++) {
                    float4 p = pr[jj][ii];
                    ak[jj][ii] = fmaf(p.x, m0, fmaf(p.y, m1, fmaf(p.z, m2, fmaf(p.w, m3, cc))));
                }
            #pragma unroll
            for (int h = 0; h < NH; h++) {
                int o = h * 32;
                float q0 = Qs[dd][o + il], q1 = Qs[dd][o + il + 1];
                float k0 = Ks[dd][o + jl], k1 = Ks[dd][o + jl + 1];
                acc[0][0][h] = fmaf(q0*k0, ak[0][0], acc[0][0][h]);
                acc[0][1][h] = fmaf(q1*k0, ak[0][1], acc[0][1][h]);
                acc[1][0][h] = fmaf(q0*k1, ak[1][0], acc[1][0][h]);
                acc[1][1][h] = fmaf(q1*k1, ak[1][1], acc[1][1][h]);
            }
        }
    }
    #pragma unroll
    for (int h = 0; h < NH; h++)
        #pragma unroll
        for (int jj = 0; jj < 2; jj++)
            #pragma unroll
            for (int ii = 0; ii < 2; ii++)
                attn[(((size_t)(b*NH + h) * NSEQ) + j0 + jl + jj) * NSEQ + i0 + il + ii] =
                    acc[jj][ii][h] * INV_T;
}

// ---------------- softmax over i (in-place on attn) + attn @ V -------------
__global__ __launch_bounds__(256)
void softmax_av_kernel(float* __restrict__ attn)
{
    int j = blockIdx.x, h = blockIdx.y, b = blockIdx.z;
    int tid = threadIdx.x;
    float* row = attn + (((size_t)(b*NH + h) * NSEQ) + j) * NSEQ;

    __shared__ float sp[NSEQ];
    __shared__ float redm[8];
    __shared__ float reds[8];
    __shared__ float pacc[4][64];

    float v0 = row[tid], v1 = row[tid + 256];
    float m = warp_max(fmaxf(v0, v1));
    if ((tid & 31) == 0) redm[tid >> 5] = m;
    __syncthreads();
    m = redm[0];
    #pragma unroll
    for (int w = 1; w < 8; w++) m = fmaxf(m, redm[w]);

    float e0 = __expf(v0 - m), e1 = __expf(v1 - m);
    float s = warp_sum(e0 + e1);
    if ((tid & 31) == 0) reds[tid >> 5] = s;
    __syncthreads();
    s = reds[0];
    #pragma unroll
    for (int w = 1; w < 8; w++) s += reds[w];

    float inv = 1.0f / s;
    e0 *= inv; e1 *= inv;
    row[tid]       = e0;
    row[tid + 256] = e1;
    sp[tid]        = e0;
    sp[tid + 256]  = e1;
    __syncthreads();

    // attn @ V : out[b,h,j,dv]  ->  g_heads[b, j, h*64+dv]
    int dv = tid & 63, part = tid >> 6;    // 4 parts of 128 i's
    const float* vb = g_v + ((size_t)(b*NH + h) * NSEQ) * DK + dv + (size_t)(part * 128) * DK;
    const float* pp = sp + part * 128;
    float a = 0.f;
    #pragma unroll 4
    for (int i = 0; i < 128; i++) a = fmaf(pp[i], vb[(size_t)i * DK], a);
    pacc[part][dv] = a;
    __syncthreads();
    if (tid < 64) {
        float s4 = pacc[0][tid] + pacc[1][tid] + pacc[2][tid] + pacc[3][tid];
        g_heads[((size_t)(b*NSEQ + j)) * DMODEL + h*DK + tid] = s4;
    }
}

// ---------------- layer norm (one token per block) --------------------------
__global__ __launch_bounds__(256)
void layernorm_kernel(const float* __restrict__ x, const float* __restrict__ gam,
                      const float* __restrict__ bet, float* __restrict__ out)
{
    int t = blockIdx.x, tid = threadIdx.x;
    const float* xr = x + (size_t)t * DMODEL;
    __shared__ float red[8];

    float a0 = xr[tid], a1 = xr[tid + 256];
    float s = warp_sum(a0 + a1);
    if ((tid & 31) == 0) red[tid >> 5] = s;
    __syncthreads();
    s = red[0];
    #pragma unroll
    for (int w = 1; w < 8; w++) s += red[w];
    float mu = s * (1.0f / DMODEL);
    float d0 = a0 - mu, d1 = a1 - mu;
    __syncthreads();

    float q = warp_sum(d0*d0 + d1*d1);
    if ((tid & 31) == 0) red[tid >> 5] = q;
    __syncthreads();
    q = red[0];
    #pragma unroll
    for (int w = 1; w < 8; w++) q += red[w];
    float inv = rsqrtf(q * (1.0f / DMODEL) + LN_EPS);

    float* orow = out + (size_t)t * DMODEL;
    orow[tid]       = d0 * inv * gam[tid]       + bet[tid];
    orow[tid + 256] = d1 * inv * gam[tid + 256] + bet[tid + 256];
}

// ---------------- launch ----------------------------------------------------
extern "C" void kernel_launch(void* const* d_in, const int* in_sizes, int n_in,
                              void* d_out, int out_size)
{
    (void)in_sizes; (void)n_in; (void)out_size;
    const float* enc    = (const float*)d_in[0];
    const float* pos    = (const float*)d_in[1];
    const float* w_qs   = (const float*)d_in[2];
    const float* w_ks   = (const float*)d_in[3];
    const float* w_vs   = (const float*)d_in[4];
    const float* w_fc   = (const float*)d_in[5];
    const float* rp_w1  = (const float*)d_in[6];
    const float* rp_b1  = (const float*)d_in[7];
    const float* rp_w2  = (const float*)d_in[8];
    const float* rp_b2  = (const float*)d_in[9];
    const float* ln1_g  = (const float*)d_in[10];
    const float* ln1_b  = (const float*)d_in[11];
    const float* ln2_g  = (const float*)d_in[12];
    const float* ln2_b  = (const float*)d_in[13];
    const float* ffn_w1 = (const float*)d_in[14];
    const float* ffn_b1 = (const float*)d_in[15];
    const float* ffn_w2 = (const float*)d_in[16];
    const float* ffn_b2 = (const float*)d_in[17];

    float* out2 = (float*)d_out;                          // [4,512,512]
    float* attn = out2 + (size_t)TOK * DMODEL;            // [4,8,512,512]

    float *pq, *pk, *pv, *pheads, *ptmp1, *pln1, *pffh, *ptmp2;
    cudaGetSymbolAddress((void**)&pq,     g_q);
    cudaGetSymbolAddress((void**)&pk,     g_k);
    cudaGetSymbolAddress((void**)&pv,     g_v);
    cudaGetSymbolAddress((void**)&pheads, g_heads);
    cudaGetSymbolAddress((void**)&ptmp1,  g_tmp1);
    cudaGetSymbolAddress((void**)&pln1,   g_ln1);
    cudaGetSymbolAddress((void**)&pffh,   g_ffh);
    cudaGetSymbolAddress((void**)&ptmp2,  g_tmp2);

    // 1) collapse rel-pos MLP
    rp_combine_kernel<<<1, 64>>>(rp_w1, rp_b1, rp_w2, rp_b2);

    // 2) Q,K,V projections: [2048,512] @ [512,512]^T -> [b,h,n,d]
    dim3 gproj(DMODEL/64, TOK/64);           // (8, 32)
    gemm_nt_kernel<false,false,false,true><<<gproj, 256>>>(enc, w_qs, nullptr, nullptr, pq, TOK, DMODEL, DMODEL);
    gemm_nt_kernel<false,false,false,true><<<gproj, 256>>>(enc, w_ks, nullptr, nullptr, pk, TOK, DMODEL, DMODEL);
    gemm_nt_kernel<false,false,false,true><<<gproj, 256>>>(enc, w_vs, nullptr, nullptr, pv, TOK, DMODEL, DMODEL);

    // 3) fused relative-position attention logits
    dim3 gsc(NSEQ/32, NSEQ/32, BB);          // (16, 16, 4)
    scores_kernel<<<gsc, 256>>>(pos, attn);

    // 4) softmax (writes normalized attn to d_out) + attn @ V
    dim3 gsm(NSEQ, NH, BB);                  // (512, 8, 4)
    softmax_av_kernel<<<gsm, 256>>>(attn);

    // 5) fc + residual(enc)  -> g_tmp1 ; LN1 -> g_ln1
    gemm_nt_kernel<false,false,true,false><<<gproj, 256>>>(pheads, w_fc, nullptr, enc, ptmp1, TOK, DMODEL, DMODEL);
    layernorm_kernel<<<TOK, 256>>>(ptmp1, ln1_g, ln1_b, pln1);

    // 6) FFN
    dim3 gff1(DINNER/64, TOK/64);            // (32, 32)
    gemm_nt_kernel<true,true,false,false><<<gff1, 256>>>(pln1, ffn_w1, ffn_b1, nullptr, pffh, TOK, DINNER, DMODEL);
    gemm_nt_kernel<true,false,true,false><<<gproj, 256>>>(pffh, ffn_w2, ffn_b2, pln1, ptmp2, TOK, DMODEL, DINNER);

    // 7) LN2 -> out2
    layernorm_kernel<<<TOK, 256>>>(ptmp2, ln2_g, ln2_b, out2);
}

// round 7
// speedup vs baseline: 1.1440x; 1.1440x over previous
#include <cuda_runtime.h>
#include <math.h>

#define BB      4
#define NSEQ    512
#define DMODEL  512
#define NH      8
#define DK      64
#define TOK     (BB*NSEQ)      // 2048
#define DINNER  2048
#define LN_EPS  1e-6f
#define INV_T   0.125f         // 1/sqrt(64)

// ---------------- scratch (no allocation allowed -> __device__ globals) ----
__device__ float g_q[BB*NH*NSEQ*DK];        // [b,h,n,d]
__device__ float g_k[BB*NH*NSEQ*DK];        // [b,h,n,d]
__device__ float g_v[BB*NH*NSEQ*DK];        // [b,h,n,d]
__device__ float g_Mmat[DK*4];              // combined rp matrix  M[d][p]
__device__ float g_cvec[DK];                // combined rp bias    c[d]
__device__ float g_heads[TOK*DMODEL];       // [b,n, h*dv]
__device__ float g_tmp1[TOK*DMODEL];        // fc + residual (pre-LN1)
__device__ float g_ln1[TOK*DMODEL];         // LN1 out (FFN residual)
__device__ float g_ffh[TOK*DINNER];         // relu(FFN hidden)
__device__ float g_tmp2[TOK*DMODEL];        // FFN out + residual (pre-LN2)

// ---------------- warp reduce helpers --------------------------------------
__device__ __forceinline__ float warp_sum(float v) {
    #pragma unroll
    for (int o = 16; o; o >>= 1) v += __shfl_xor_sync(0xffffffffu, v, o);
    return v;
}
__device__ __forceinline__ float warp_max(float v) {
    #pragma unroll
    for (int o = 16; o; o >>= 1) v = fmaxf(v, __shfl_xor_sync(0xffffffffu, v, o));
    return v;
}

// ---------------- collapse rel-pos MLP: M = W2@W1, c = W2@b1 + b2 ----------
__global__ void rp_combine_kernel(const float* __restrict__ w1, const float* __restrict__ b1,
                                  const float* __restrict__ w2, const float* __restrict__ b2) {
    int d = threadIdx.x;
    if (d >= DK) return;
    float m0 = 0.f, m1 = 0.f, m2 = 0.f, m3 = 0.f, cc = 0.f;
    for (int k = 0; k < DK; k++) {
        float w = w2[d*DK + k];
        m0 = fmaf(w, w1[k*4+0], m0);
        m1 = fmaf(w, w1[k*4+1], m1);
        m2 = fmaf(w, w1[k*4+2], m2);
        m3 = fmaf(w, w1[k*4+3], m3);
        cc = fmaf(w, b1[k],      cc);
    }
    g_Mmat[d*4+0] = m0; g_Mmat[d*4+1] = m1;
    g_Mmat[d*4+2] = m2; g_Mmat[d*4+3] = m3;
    g_cvec[d] = cc + b2[d];
}

// ============================================================================
// SGEMM: C = A @ B^T (BTRANS=true, B:[N,K]) or C = A @ B (BTRANS=false, B:[K,N])
// TM=128, TN in {128, 64}, BK=8, 256 threads, double-buffered smem,
// micro-tile 8 x (TN/16) per thread.
// MAP: 0 = plain C[r*N+c]   1 = QKV split-head remap (writes g_q/g_k/g_v)
//      2 = AV head-concat remap (writes g_heads)
// ============================================================================
template<int TN, int MAP, bool BTRANS, bool BIAS, bool RELU, bool RESID>
__global__ __launch_bounds__(256)
void sgemm_kernel(const float* __restrict__ A,
                  const float* __restrict__ B0, const float* __restrict__ B1,
                  const float* __restrict__ B2,
                  const float* __restrict__ bias, const float* __restrict__ resid,
                  float* __restrict__ C, int M, int N, int K,
                  size_t strideA, size_t strideB)
{
    constexpr int TNF = TN / 16;           // 8 or 4 cols per thread
    __shared__ float As[2][8][132];
    __shared__ float Bs[2][8][TN + 4];

    int tid  = threadIdx.x;
    int tx   = tid & 15, ty = tid >> 4;
    int row0 = blockIdx.y << 7;
    int col0 = blockIdx.x * TN;
    int z    = blockIdx.z;

    const float* Ab = A + (size_t)z * strideA;
    const float* Bb;
    if (MAP == 1) {
        int w = col0 >> 9;
        const float* Bw = (w == 0) ? B0 : ((w == 1) ? B1 : B2);
        Bb = Bw + (size_t)(col0 & 511) * K;
    } else if (BTRANS) {
        Bb = B0 + (size_t)z * strideB + (size_t)col0 * K;
    } else {
        Bb = B0 + (size_t)z * strideB + col0;
    }

    // A tile loader: 128 rows x 8 k, one float4/thread
    int arow = tid >> 1, acol = (tid & 1) << 2;
    const float* Aload = Ab + (size_t)(row0 + arow) * K + acol;

    // B tile loader
    int brow = tid >> 1, bk = (tid & 1) << 2;        // BTRANS: row-of-B(=out col), k
    int krow = tid >> 4, bcol = (tid & 15) << 2;     // !BTRANS: k row, col
    const float* BloadT = Bb + (size_t)brow * K + bk;
    const float* BloadN = Bb + (size_t)krow * N + bcol;

    float acc[8][TNF];
    #pragma unroll
    for (int i = 0; i < 8; i++)
        #pragma unroll
        for (int j = 0; j < TNF; j++) acc[i][j] = 0.f;

    auto ldA = [&](int k0) { return *(const float4*)(Aload + k0); };
    auto ldB = [&](int k0) {
        float4 v = make_float4(0.f, 0.f, 0.f, 0.f);
        if (BTRANS) { if (tid < TN * 2) v = *(const float4*)(BloadT + k0); }
        else        { if (tid < 128)    v = *(const float4*)(BloadN + (size_t)k0 * N); }
        return v;
    };
    auto stTile = [&](int buf, float4 av, float4 bv) {
        As[buf][acol+0][arow] = av.x; As[buf][acol+1][arow] = av.y;
        As[buf][acol+2][arow] = av.z; As[buf][acol+3][arow] = av.w;
        if (BTRANS) {
            if (tid < TN * 2) {
                Bs[buf][bk+0][brow] = bv.x; Bs[buf][bk+1][brow] = bv.y;
                Bs[buf][bk+2][brow] = bv.z; Bs[buf][bk+3][brow] = bv.w;
            }
        } else {
            if (tid < 128) *(float4*)&Bs[buf][krow][bcol] = bv;
        }
    };
    auto compute = [&](int buf) {
        #pragma unroll
        for (int kk = 0; kk < 8; kk++) {
            float4 a0 = *(const float4*)&As[buf][kk][ty << 3];
            float4 a1 = *(const float4*)&As[buf][kk][(ty << 3) + 4];
            float aa[8] = {a0.x, a0.y, a0.z, a0.w, a1.x, a1.y, a1.z, a1.w};
            float bb[TNF];
            float4 b0 = *(const float4*)&Bs[buf][kk][tx * TNF];
            bb[0] = b0.x; bb[1] = b0.y; bb[2] = b0.z; bb[3] = b0.w;
            if (TNF == 8) {
                float4 b1 = *(const float4*)&Bs[buf][kk][tx * TNF + 4];
                bb[4] = b1.x; bb[5] = b1.y; bb[6] = b1.z; bb[7] = b1.w;
            }
            #pragma unroll
            for (int i = 0; i < 8; i++)
                #pragma unroll
                for (int j = 0; j < TNF; j++)
                    acc[i][j] = fmaf(aa[i], bb[j], acc[i][j]);
        }
    };

    // prologue
    {
        float4 av = ldA(0), bv = ldB(0);
        stTile(0, av, bv);
    }
    __syncthreads();
    int buf = 0;
    for (int k0 = 8; k0 < K; k0 += 8) {
        float4 av = ldA(k0), bv = ldB(k0);
        compute(buf);
        stTile(buf ^ 1, av, bv);
        __syncthreads();
        buf ^= 1;
    }
    compute(buf);

    // ---------------- epilogue (float4 stores) ----------------
    #pragma unroll
    for (int ii = 0; ii < 8; ii++) {
        int r = row0 + (ty << 3) + ii;
        #pragma unroll
        for (int j4 = 0; j4 < TNF / 4; j4++) {
            int c = col0 + tx * TNF + j4 * 4;
            float4 v = make_float4(acc[ii][j4*4+0], acc[ii][j4*4+1],
                                   acc[ii][j4*4+2], acc[ii][j4*4+3]);
            if (BIAS) {
                float4 bz = *(const float4*)(bias + c);
                v.x += bz.x; v.y += bz.y; v.z += bz.z; v.w += bz.w;
            }
            if (RESID) {
                float4 rz = *(const float4*)(resid + (size_t)r * N + c);
                v.x += rz.x; v.y += rz.y; v.z += rz.z; v.w += rz.w;
            }
            if (RELU) {
                v.x = fmaxf(v.x, 0.f); v.y = fmaxf(v.y, 0.f);
                v.z = fmaxf(v.z, 0.f); v.w = fmaxf(v.w, 0.f);
            }
            if (MAP == 0) {
                *(float4*)(C + (size_t)r * N + c) = v;
            } else if (MAP == 1) {
                int w  = c >> 9, cc = c & 511;
                int h  = cc >> 6, d = cc & 63;
                int b  = r >> 9, n = r & 511;
                float* dst = (w == 0) ? g_q : ((w == 1) ? g_k : g_v);
                *(float4*)(dst + ((((size_t)b * NH + h) * NSEQ) + n) * DK + d) = v;
            } else { // MAP == 2: z = b*8+h, r = j, c = dv
                int b = z >> 3, h = z & 7;
                *(float4*)(g_heads + ((size_t)(b * NSEQ) + r) * DMODEL + h * DK + c) = v;
            }
        }
    }
}

// ---------------- fused relative attention scores ---------------------------
// attn_raw[b,h,j,i] = (1/T) * sum_d q[b,h,i,d]*k[b,h,j,d]*(c[d] + pos[b,j,i,:]·M[d,:])
__global__ __launch_bounds__(256)
void scores_kernel(const float* __restrict__ pos, float* __restrict__ attn)
{
    __shared__ float Qs[16][256];  // [dd][h*32 + i_local]
    __shared__ float Ks[16][256];  // [dd][h*32 + j_local]
    __shared__ float Ms[DK*4];
    __shared__ float Cs[DK];

    int tid = threadIdx.x;
    int b   = blockIdx.z;
    int i0  = blockIdx.x << 5, j0 = blockIdx.y << 5;
    int tx  = tid & 15, ty = tid >> 4;
    int il  = tx << 1, jl = ty << 1;

    Ms[tid] = g_Mmat[tid];
    if (tid < DK) Cs[tid] = g_cvec[tid];

    float4 pr[2][2];
    #pragma unroll
    for (int jj = 0; jj < 2; jj++)
        #pragma unroll
        for (int ii = 0; ii < 2; ii++)
            pr[jj][ii] = *(const float4*)(pos +
                (((size_t)(b*NSEQ + j0 + jl + jj) * NSEQ) + (i0 + il + ii)) * 4);

    float acc[2][2][NH];
    #pragma unroll
    for (int jj = 0; jj < 2; jj++)
        #pragma unroll
        for (int ii = 0; ii < 2; ii++)
            #pragma unroll
            for (int h = 0; h < NH; h++) acc[jj][ii][h] = 0.f;

    int fh = tid >> 5, fi = tid & 31;
    const float* qb = g_q + (((size_t)(b*NH + fh) * NSEQ) + i0 + fi) * DK;
    const float* kb = g_k + (((size_t)(b*NH + fh) * NSEQ) + j0 + fi) * DK;
    int base = fh * 32 + fi;

    for (int dc = 0; dc < DK; dc += 16) {
        __syncthreads();
        #pragma unroll
        for (int c4 = 0; c4 < 4; c4++) {
            float4 qv = *(const float4*)(qb + dc + c4*4);
            float4 kv = *(const float4*)(kb + dc + c4*4);
            Qs[c4*4+0][base] = qv.x; Qs[c4*4+1][base] = qv.y;
            Qs[c4*4+2][base] = qv.z; Qs[c4*4+3][base] = qv.w;
            Ks[c4*4+0][base] = kv.x; Ks[c4*4+1][base] = kv.y;
            Ks[c4*4+2][base] = kv.z; Ks[c4*4+3][base] = kv.w;
        }
        __syncthreads();
        #pragma unroll
        for (int dd = 0; dd < 16; dd++) {
            int d = dc + dd;
            float m0 = Ms[d*4+0], m1 = Ms[d*4+1], m2 = Ms[d*4+2], m3 = Ms[d*4+3];
            float cc = Cs[d];
            float ak[2][2];
            #pragma unroll
            for (int jj = 0; jj < 2; jj++)
                #pragma unroll
                for (int ii = 0; ii < 2; ii++) {
                    float4 p = pr[jj][ii];
                    ak[jj][ii] = fmaf(p.x, m0, fmaf(p.y, m1, fmaf(p.z, m2, fmaf(p.w, m3, cc))));
                }
            #pragma unroll
            for (int h = 0; h < NH; h++) {
                int o = h * 32;
                float q0 = Qs[dd][o + il], q1 = Qs[dd][o + il + 1];
                float k0 = Ks[dd][o + jl], k1 = Ks[dd][o + jl + 1];
                acc[0][0][h] = fmaf(q0*k0, ak[0][0], acc[0][0][h]);
                acc[0][1][h] = fmaf(q1*k0, ak[0][1], acc[0][1][h]);
                acc[1][0][h] = fmaf(q0*k1, ak[1][0], acc[1][0][h]);
                acc[1][1][h] = fmaf(q1*k1, ak[1][1], acc[1][1][h]);
            }
        }
    }
    #pragma unroll
    for (int h = 0; h < NH; h++)
        #pragma unroll
        for (int jj = 0; jj < 2; jj++)
            #pragma unroll
            for (int ii = 0; ii < 2; ii++)
                attn[(((size_t)(b*NH + h) * NSEQ) + j0 + jl + jj) * NSEQ + i0 + il + ii] =
                    acc[jj][ii][h] * INV_T;
}

// ---------------- softmax over last axis, in place ---------------------------
__global__ __launch_bounds__(256)
void softmax_kernel(float* __restrict__ attn)
{
    size_t row = blockIdx.x;
    float* p = attn + row * NSEQ;
    int tid = threadIdx.x;
    __shared__ float redm[8];
    __shared__ float reds[8];

    float v0 = p[tid], v1 = p[tid + 256];
    float m = warp_max(fmaxf(v0, v1));
    if ((tid & 31) == 0) redm[tid >> 5] = m;
    __syncthreads();
    m = redm[0];
    #pragma unroll
    for (int w = 1; w < 8; w++) m = fmaxf(m, redm[w]);

    float e0 = __expf(v0 - m), e1 = __expf(v1 - m);
    float s = warp_sum(e0 + e1);
    if ((tid & 31) == 0) reds[tid >> 5] = s;
    __syncthreads();
    s = reds[0];
    #pragma unroll
    for (int w = 1; w < 8; w++) s += reds[w];

    float inv = 1.0f / s;
    p[tid]       = e0 * inv;
    p[tid + 256] = e1 * inv;
}

// ---------------- layer norm (one token per block) --------------------------
__global__ __launch_bounds__(256)
void layernorm_kernel(const float* __restrict__ x, const float* __restrict__ gam,
                      const float* __restrict__ bet, float* __restrict__ out)
{
    int t = blockIdx.x, tid = threadIdx.x;
    const float* xr = x + (size_t)t * DMODEL;
    __shared__ float red[8];

    float a0 = xr[tid], a1 = xr[tid + 256];
    float s = warp_sum(a0 + a1);
    if ((tid & 31) == 0) red[tid >> 5] = s;
    __syncthreads();
    s = red[0];
    #pragma unroll
    for (int w = 1; w < 8; w++) s += red[w];
    float mu = s * (1.0f / DMODEL);
    float d0 = a0 - mu, d1 = a1 - mu;
    __syncthreads();

    float q = warp_sum(d0*d0 + d1*d1);
    if ((tid & 31) == 0) red[tid >> 5] = q;
    __syncthreads();
    q = red[0];
    #pragma unroll
    for (int w = 1; w < 8; w++) q += red[w];
    float inv = rsqrtf(q * (1.0f / DMODEL) + LN_EPS);

    float* orow = out + (size_t)t * DMODEL;
    orow[tid]       = d0 * inv * gam[tid]       + bet[tid];
    orow[tid + 256] = d1 * inv * gam[tid + 256] + bet[tid + 256];
}

// ---------------- launch ----------------------------------------------------
extern "C" void kernel_launch(void* const* d_in, const int* in_sizes, int n_in,
                              void* d_out, int out_size)
{
    (void)in_sizes; (void)n_in; (void)out_size;
    const float* enc    = (const float*)d_in[0];
    const float* pos    = (const float*)d_in[1];
    const float* w_qs   = (const float*)d_in[2];
    const float* w_ks   = (const float*)d_in[3];
    const float* w_vs   = (const float*)d_in[4];
    const float* w_fc   = (const float*)d_in[5];
    const float* rp_w1  = (const float*)d_in[6];
    const float* rp_b1  = (const float*)d_in[7];
    const float* rp_w2  = (const float*)d_in[8];
    const float* rp_b2  = (const float*)d_in[9];
    const float* ln1_g  = (const float*)d_in[10];
    const float* ln1_b  = (const float*)d_in[11];
    const float* ln2_g  = (const float*)d_in[12];
    const float* ln2_b  = (const float*)d_in[13];
    const float* ffn_w1 = (const float*)d_in[14];
    const float* ffn_b1 = (const float*)d_in[15];
    const float* ffn_w2 = (const float*)d_in[16];
    const float* ffn_b2 = (const float*)d_in[17];

    float* out2 = (float*)d_out;                          // [4,512,512]
    float* attn = out2 + (size_t)TOK * DMODEL;            // [4,8,512,512]

    float *pq, *pv, *pheads, *ptmp1, *pln1, *pffh, *ptmp2;
    cudaGetSymbolAddress((void**)&pq,     g_q);
    cudaGetSymbolAddress((void**)&pv,     g_v);
    cudaGetSymbolAddress((void**)&pheads, g_heads);
    cudaGetSymbolAddress((void**)&ptmp1,  g_tmp1);
    cudaGetSymbolAddress((void**)&pln1,   g_ln1);
    cudaGetSymbolAddress((void**)&pffh,   g_ffh);
    cudaGetSymbolAddress((void**)&ptmp2,  g_tmp2);

    // 1) collapse rel-pos MLP
    rp_combine_kernel<<<1, 64>>>(rp_w1, rp_b1, rp_w2, rp_b2);

    // 2) fused QKV projection: [2048,512] @ [512,1536]^T -> g_q/g_k/g_v [b,h,n,d]
    {
        dim3 g(1536/128, TOK/128, 1);  // (12,16)
        sgemm_kernel<128, 1, true, false, false, false><<<g, 256>>>(
            enc, w_qs, w_ks, w_vs, nullptr, nullptr, nullptr, TOK, 1536, DMODEL, 0, 0);
    }

    // 3) fused relative-position attention logits -> attn (pre-softmax, /T)
    {
        dim3 g(NSEQ/32, NSEQ/32, BB);
        scores_kernel<<<g, 256>>>(pos, attn);
    }

    // 4) softmax in place (normalized attn is part of the output)
    softmax_kernel<<<BB*NH*NSEQ, 256>>>(attn);

    // 5) AV: per (b,h): P[512,512] @ V[512,64] -> g_heads[b,n,h*64+dv]
    {
        dim3 g(1, NSEQ/128, BB*NH);    // (1,4,32)
        sgemm_kernel<64, 2, false, false, false, false><<<g, 256>>>(
            attn, pv, pv, pv, nullptr, nullptr, nullptr,
            NSEQ, DK, NSEQ, (size_t)NSEQ*NSEQ, (size_t)NSEQ*DK);
    }

    // 6) fc + residual(enc) -> g_tmp1 ; LN1 -> g_ln1
    {
        dim3 g(DMODEL/64, TOK/128, 1); // (8,16)
        sgemm_kernel<64, 0, true, false, false, true><<<g, 256>>>(
            pheads, w_fc, w_fc, w_fc, nullptr, enc, ptmp1, TOK, DMODEL, DMODEL, 0, 0);
    }
    layernorm_kernel<<<TOK, 256>>>(ptmp1, ln1_g, ln1_b, pln1);

    // 7) FFN1: relu(ln1 @ W1^T + b1) -> g_ffh
    {
        dim3 g(DINNER/128, TOK/128, 1); // (16,16)
        sgemm_kernel<128, 0, true, true, true, false><<<g, 256>>>(
            pln1, ffn_w1, ffn_w1, ffn_w1, ffn_b1, nullptr, pffh, TOK, DINNER, DMODEL, 0, 0);
    }

    // 8) FFN2: ffh @ W2^T + b2 + ln1 -> g_tmp2
    {
        dim3 g(DMODEL/64, TOK/128, 1); // (8,16)
        sgemm_kernel<64, 0, true, true, false, true><<<g, 256>>>(
            pffh, ffn_w2, ffn_w2, ffn_w2, ffn_b2, pln1, ptmp2, TOK, DMODEL, DINNER, 0, 0);
    }

    // 9) LN2 -> out2
    layernorm_kernel<<<TOK, 256>>>(ptmp2, ln2_g, ln2_b, out2);
}

// round 8
// speedup vs baseline: 1.5805x; 1.3815x over previous
#include <cuda_runtime.h>
#include <math.h>
#include <stdint.h>

#define BB      4
#define NSEQ    512
#define DMODEL  512
#define NH      8
#define DK      64
#define TOK     (BB*NSEQ)      // 2048
#define DINNER  2048
#define LN_EPS  1e-6f
#define INV_T   0.125f         // 1/sqrt(64)

// ---------------- scratch (no allocation allowed -> __device__ globals) ----
__device__ float g_q[BB*NH*NSEQ*DK];        // [b,h,n,d]
__device__ float g_k[BB*NH*NSEQ*DK];        // [b,h,n,d]
__device__ float g_v[BB*NH*NSEQ*DK];        // [b,h,n,d]
__device__ float g_Mmat[DK*4];              // combined rp matrix  M[d][p]
__device__ float g_cvec[DK];                // combined rp bias    c[d]
__device__ float g_heads[TOK*DMODEL];       // [b,n, h*dv]
__device__ float g_tmp1[TOK*DMODEL];        // fc + residual (pre-LN1)
__device__ float g_ln1[TOK*DMODEL];         // LN1 out (FFN residual)
__device__ float g_ffh[TOK*DINNER];         // relu(FFN hidden)
__device__ float g_tmp2[TOK*DMODEL];        // FFN out + residual (pre-LN2)

// ---------------- helpers ---------------------------------------------------
__device__ __forceinline__ float warp_sum(float v) {
    #pragma unroll
    for (int o = 16; o; o >>= 1) v += __shfl_xor_sync(0xffffffffu, v, o);
    return v;
}
__device__ __forceinline__ float warp_max(float v) {
    #pragma unroll
    for (int o = 16; o; o >>= 1) v = fmaxf(v, __shfl_xor_sync(0xffffffffu, v, o));
    return v;
}
__device__ __forceinline__ float to_tf32(float x) {
    uint32_t u;
    asm("cvt.rna.tf32.f32 %0, %1;" : "=r"(u) : "f"(x));
    return __uint_as_float(u);
}
__device__ __forceinline__ void mma_tf32(float (&c)[4], const uint32_t (&a)[4],
                                         const uint32_t (&b)[2]) {
    asm volatile(
        "mma.sync.aligned.m16n8k8.row.col.f32.tf32.tf32.f32 "
        "{%0,%1,%2,%3}, {%4,%5,%6,%7}, {%8,%9}, {%0,%1,%2,%3};\n"
        : "+f"(c[0]), "+f"(c[1]), "+f"(c[2]), "+f"(c[3])
        : "r"(a[0]), "r"(a[1]), "r"(a[2]), "r"(a[3]), "r"(b[0]), "r"(b[1]));
}

// ---------------- collapse rel-pos MLP: M = W2@W1, c = W2@b1 + b2 ----------
__global__ void rp_combine_kernel(const float* __restrict__ w1, const float* __restrict__ b1,
                                  const float* __restrict__ w2, const float* __restrict__ b2) {
    int d = threadIdx.x;
    if (d >= DK) return;
    float m0 = 0.f, m1 = 0.f, m2 = 0.f, m3 = 0.f, cc = 0.f;
    for (int k = 0; k < DK; k++) {
        float w = w2[d*DK + k];
        m0 = fmaf(w, w1[k*4+0], m0);
        m1 = fmaf(w, w1[k*4+1], m1);
        m2 = fmaf(w, w1[k*4+2], m2);
        m3 = fmaf(w, w1[k*4+3], m3);
        cc = fmaf(w, b1[k],      cc);
    }
    g_Mmat[d*4+0] = m0; g_Mmat[d*4+1] = m1;
    g_Mmat[d*4+2] = m2; g_Mmat[d*4+3] = m3;
    g_cvec[d] = cc + b2[d];
}

// ============================================================================
// fp32 SGEMM (kept ONLY for the QKV projection, which feeds the exact attn
// output path): C = A @ B^T, 128x128 tile, BK=8, double-buffered, MAP=QKV.
// ============================================================================
__global__ __launch_bounds__(256)
void sgemm_qkv_kernel(const float* __restrict__ A,
                      const float* __restrict__ B0, const float* __restrict__ B1,
                      const float* __restrict__ B2, int K)
{
    __shared__ float As[2][8][132];
    __shared__ float Bs[2][8][132];

    int tid  = threadIdx.x;
    int tx   = tid & 15, ty = tid >> 4;
    int row0 = blockIdx.y << 7;
    int col0 = blockIdx.x << 7;

    int w = col0 >> 9;
    const float* Bw = (w == 0) ? B0 : ((w == 1) ? B1 : B2);
    const float* Bb = Bw + (size_t)(col0 & 511) * K;

    int arow = tid >> 1, acol = (tid & 1) << 2;
    const float* Aload = A + (size_t)(row0 + arow) * K + acol;
    const float* Bload = Bb + (size_t)arow * K + acol;

    float acc[8][8];
    #pragma unroll
    for (int i = 0; i < 8; i++)
        #pragma unroll
        for (int j = 0; j < 8; j++) acc[i][j] = 0.f;

    auto stTile = [&](int buf, float4 av, float4 bv) {
        As[buf][acol+0][arow] = av.x; As[buf][acol+1][arow] = av.y;
        As[buf][acol+2][arow] = av.z; As[buf][acol+3][arow] = av.w;
        Bs[buf][acol+0][arow] = bv.x; Bs[buf][acol+1][arow] = bv.y;
        Bs[buf][acol+2][arow] = bv.z; Bs[buf][acol+3][arow] = bv.w;
    };
    auto compute = [&](int buf) {
        #pragma unroll
        for (int kk = 0; kk < 8; kk++) {
            float4 a0 = *(const float4*)&As[buf][kk][ty << 3];
            float4 a1 = *(const float4*)&As[buf][kk][(ty << 3) + 4];
            float4 b0 = *(const float4*)&Bs[buf][kk][tx << 3];
            float4 b1 = *(const float4*)&Bs[buf][kk][(tx << 3) + 4];
            float aa[8] = {a0.x, a0.y, a0.z, a0.w, a1.x, a1.y, a1.z, a1.w};
            float bb[8] = {b0.x, b0.y, b0.z, b0.w, b1.x, b1.y, b1.z, b1.w};
            #pragma unroll
            for (int i = 0; i < 8; i++)
                #pragma unroll
                for (int j = 0; j < 8; j++)
                    acc[i][j] = fmaf(aa[i], bb[j], acc[i][j]);
        }
    };

    {
        float4 av = *(const float4*)(Aload);
        float4 bv = *(const float4*)(Bload);
        stTile(0, av, bv);
    }
    __syncthreads();
    int buf = 0;
    for (int k0 = 8; k0 < K; k0 += 8) {
        float4 av = *(const float4*)(Aload + k0);
        float4 bv = *(const float4*)(Bload + k0);
        compute(buf);
        stTile(buf ^ 1, av, bv);
        __syncthreads();
        buf ^= 1;
    }
    compute(buf);

    #pragma unroll
    for (int ii = 0; ii < 8; ii++) {
        int r = row0 + (ty << 3) + ii;
        #pragma unroll
        for (int j4 = 0; j4 < 2; j4++) {
            int c = col0 + (tx << 3) + j4 * 4;
            float4 v = make_float4(acc[ii][j4*4+0], acc[ii][j4*4+1],
                                   acc[ii][j4*4+2], acc[ii][j4*4+3]);
            int wsel = c >> 9, cc = c & 511;
            int h  = cc >> 6, d = cc & 63;
            int b  = r >> 9, n = r & 511;
            float* dst = (wsel == 0) ? g_q : ((wsel == 1) ? g_k : g_v);
            *(float4*)(dst + ((((size_t)b * NH + h) * NSEQ) + n) * DK + d) = v;
        }
    }
}

// ============================================================================
// TF32 tensor-core GEMM.
//   BTRANS=true : C = A @ B^T,  B:[N,K] row-major  (fc, ffn1, ffn2)
//   BTRANS=false: C = A @ B,    B:[K,N] row-major  (AV; requires TN==N==64)
// Tile 128 x TN, BK=16, 256 threads = 8 warps (2x4), warp tile 64 x (TN/4),
// mma.m16n8k8 fragments (4 m-tiles x NT n-tiles per warp).
// MAP: 0 = plain C,  2 = AV head-concat remap into g_heads.
// ============================================================================
template<int TN, int MAP, bool BTRANS, bool BIAS, bool RELU, bool RESID>
__global__ __launch_bounds__(256)
void tgemm_kernel(const float* __restrict__ A, const float* __restrict__ B0,
                  const float* __restrict__ bias, const float* __restrict__ resid,
                  float* __restrict__ C, int N, int K,
                  size_t strideA, size_t strideB)
{
    constexpr int NT   = TN / 32;                 // n-tiles per warp (4 or 2)
    constexpr int WN   = TN / 4;                  // warp n-extent (32 or 16)
    constexpr int BPAD = (TN == 128) ? 136 : 72;

    __shared__ __align__(16) float As[2][16][136];
    __shared__ __align__(16) float Bs[2][16][BPAD];

    int tid  = threadIdx.x;
    int lane = tid & 31, warp = tid >> 5;
    int wm = warp >> 2, wn = warp & 3;            // 2 x 4 warp grid
    int qr = lane >> 2, qc = lane & 3;
    int row0 = blockIdx.y << 7;
    int col0 = blockIdx.x * TN;
    int z    = blockIdx.z;

    const float* Ab = A + (size_t)z * strideA;
    const float* Bb = BTRANS ? (B0 + (size_t)col0 * K)
                             : (B0 + (size_t)z * strideB + col0);

    // global loaders
    int ar = tid >> 2, ak = (tid & 3) << 2;       // 64 rows x 16k per pass
    const float* Ald = Ab + (size_t)(row0 + ar) * K + ak;
    const float* Bld_t = Bb + (size_t)ar * K + ak;
    int bkr = tid >> 4, bn4 = (tid & 15) << 2;    // !BTRANS: 16k x 64n
    const float* Bld_n = Bb + (size_t)bkr * N + bn4;

    float acc[4][NT][4];
    #pragma unroll
    for (int mt = 0; mt < 4; mt++)
        #pragma unroll
        for (int nt = 0; nt < NT; nt++)
            #pragma unroll
            for (int c = 0; c < 4; c++) acc[mt][nt][c] = 0.f;

    float4 av[2], bv[2];
    auto ldG = [&](int k0) {
        av[0] = *(const float4*)(Ald + k0);
        av[1] = *(const float4*)(Ald + (size_t)64 * K + k0);
        if (BTRANS) {
            bv[0] = *(const float4*)(Bld_t + k0);
            if (TN == 128) bv[1] = *(const float4*)(Bld_t + (size_t)64 * K + k0);
        } else {
            bv[0] = *(const float4*)(Bld_n + (size_t)k0 * N);
        }
    };
    auto stS = [&](int buf) {
        #pragma unroll
        for (int h = 0; h < 2; h++) {
            int r = ar + h * 64;
            As[buf][ak+0][r] = to_tf32(((const float*)&av[h])[0]);
            As[buf][ak+1][r] = to_tf32(((const float*)&av[h])[1]);
            As[buf][ak+2][r] = to_tf32(((const float*)&av[h])[2]);
            As[buf][ak+3][r] = to_tf32(((const float*)&av[h])[3]);
        }
        if (BTRANS) {
            #pragma unroll
            for (int h = 0; h < (TN == 128 ? 2 : 1); h++) {
                int r = ar + h * 64;
                if (TN == 128 || r < TN) {
                    Bs[buf][ak+0][r] = to_tf32(((const float*)&bv[h])[0]);
                    Bs[buf][ak+1][r] = to_tf32(((const float*)&bv[h])[1]);
                    Bs[buf][ak+2][r] = to_tf32(((const float*)&bv[h])[2]);
                    Bs[buf][ak+3][r] = to_tf32(((const float*)&bv[h])[3]);
                }
            }
        } else {
            float4 t = make_float4(to_tf32(bv[0].x), to_tf32(bv[0].y),
                                   to_tf32(bv[0].z), to_tf32(bv[0].w));
            *(float4*)&Bs[buf][bkr][bn4] = t;
        }
    };
    auto compute = [&](int buf) {
        #pragma unroll
        for (int ks = 0; ks < 2; ks++) {
            int kb = ks * 8;
            uint32_t af[4][4], bf[NT][2];
            #pragma unroll
            for (int mt = 0; mt < 4; mt++) {
                int mb = wm * 64 + mt * 16;
                af[mt][0] = __float_as_uint(As[buf][kb+qc  ][mb+qr  ]);
                af[mt][1] = __float_as_uint(As[buf][kb+qc  ][mb+qr+8]);
                af[mt][2] = __float_as_uint(As[buf][kb+qc+4][mb+qr  ]);
                af[mt][3] = __float_as_uint(As[buf][kb+qc+4][mb+qr+8]);
            }
            #pragma unroll
            for (int nt = 0; nt < NT; nt++) {
                int nb = wn * WN + nt * 8;
                bf[nt][0] = __float_as_uint(Bs[buf][kb+qc  ][nb+qr]);
                bf[nt][1] = __float_as_uint(Bs[buf][kb+qc+4][nb+qr]);
            }
            #pragma unroll
            for (int mt = 0; mt < 4; mt++)
                #pragma unroll
                for (int nt = 0; nt < NT; nt++)
                    mma_tf32(acc[mt][nt], af[mt], bf[nt]);
        }
    };

    ldG(0);
    stS(0);
    __syncthreads();
    int buf = 0;
    for (int k0 = 16; k0 < K; k0 += 16) {
        ldG(k0);
        compute(buf);
        stS(buf ^ 1);
        __syncthreads();
        buf ^= 1;
    }
    compute(buf);

    // -------- epilogue (float2 stores) --------
    #pragma unroll
    for (int mt = 0; mt < 4; mt++) {
        int rbase = row0 + wm * 64 + mt * 16 + qr;
        #pragma unroll
        for (int nt = 0; nt < NT; nt++) {
            int cg = col0 + wn * WN + nt * 8 + 2 * qc;
            #pragma unroll
            for (int hh = 0; hh < 2; hh++) {
                int r = rbase + hh * 8;
                float2 v = make_float2(acc[mt][nt][2*hh], acc[mt][nt][2*hh+1]);
                if (BIAS) {
                    v.x += bias[cg]; v.y += bias[cg+1];
                }
                if (RESID) {
                    const float2 rz = *(const float2*)(resid + (size_t)r * N + cg);
                    v.x += rz.x; v.y += rz.y;
                }
                if (RELU) { v.x = fmaxf(v.x, 0.f); v.y = fmaxf(v.y, 0.f); }
                if (MAP == 0) {
                    *(float2*)(C + (size_t)r * N + cg) = v;
                } else { // MAP == 2: z = b*8+h, r = j, cg = dv
                    int b = z >> 3, h2 = z & 7;
                    *(float2*)(g_heads + ((size_t)(b * NSEQ) + r) * DMODEL + h2 * DK + cg) = v;
                }
            }
        }
    }
}

// ---------------- fused relative attention scores ---------------------------
// attn_raw[b,h,j,i] = (1/T) * sum_d q[b,h,i,d]*k[b,h,j,d]*(c[d] + pos[b,j,i,:]·M[d,:])
__global__ __launch_bounds__(256)
void scores_kernel(const float* __restrict__ pos, float* __restrict__ attn)
{
    __shared__ float Qs[16][256];
    __shared__ float Ks[16][256];
    __shared__ float Ms[DK*4];
    __shared__ float Cs[DK];

    int tid = threadIdx.x;
    int b   = blockIdx.z;
    int i0  = blockIdx.x << 5, j0 = blockIdx.y << 5;
    int tx  = tid & 15, ty = tid >> 4;
    int il  = tx << 1, jl = ty << 1;

    Ms[tid] = g_Mmat[tid];
    if (tid < DK) Cs[tid] = g_cvec[tid];

    float4 pr[2][2];
    #pragma unroll
    for (int jj = 0; jj < 2; jj++)
        #pragma unroll
        for (int ii = 0; ii < 2; ii++)
            pr[jj][ii] = *(const float4*)(pos +
                (((size_t)(b*NSEQ + j0 + jl + jj) * NSEQ) + (i0 + il + ii)) * 4);

    float acc[2][2][NH];
    #pragma unroll
    for (int jj = 0; jj < 2; jj++)
        #pragma unroll
        for (int ii = 0; ii < 2; ii++)
            #pragma unroll
            for (int h = 0; h < NH; h++) acc[jj][ii][h] = 0.f;

    int fh = tid >> 5, fi = tid & 31;
    const float* qb = g_q + (((size_t)(b*NH + fh) * NSEQ) + i0 + fi) * DK;
    const float* kb = g_k + (((size_t)(b*NH + fh) * NSEQ) + j0 + fi) * DK;
    int base = fh * 32 + fi;

    for (int dc = 0; dc < DK; dc += 16) {
        __syncthreads();
        #pragma unroll
        for (int c4 = 0; c4 < 4; c4++) {
            float4 qv = *(const float4*)(qb + dc + c4*4);
            float4 kv = *(const float4*)(kb + dc + c4*4);
            Qs[c4*4+0][base] = qv.x; Qs[c4*4+1][base] = qv.y;
            Qs[c4*4+2][base] = qv.z; Qs[c4*4+3][base] = qv.w;
            Ks[c4*4+0][base] = kv.x; Ks[c4*4+1][base] = kv.y;
            Ks[c4*4+2][base] = kv.z; Ks[c4*4+3][base] = kv.w;
        }
        __syncthreads();
        #pragma unroll
        for (int dd = 0; dd < 16; dd++) {
            int d = dc + dd;
            float m0 = Ms[d*4+0], m1 = Ms[d*4+1], m2 = Ms[d*4+2], m3 = Ms[d*4+3];
            float cc = Cs[d];
            float ak[2][2];
            #pragma unroll
            for (int jj = 0; jj < 2; jj++)
                #pragma unroll
                for (int ii = 0; ii < 2; ii++) {
                    float4 p = pr[jj][ii];
                    ak[jj][ii] = fmaf(p.x, m0, fmaf(p.y, m1, fmaf(p.z, m2, fmaf(p.w, m3, cc))));
                }
            #pragma unroll
            for (int h = 0; h < NH; h++) {
                int o = h * 32;
                float q0 = Qs[dd][o + il], q1 = Qs[dd][o + il + 1];
                float k0 = Ks[dd][o + jl], k1 = Ks[dd][o + jl + 1];
                acc[0][0][h] = fmaf(q0*k0, ak[0][0], acc[0][0][h]);
                acc[0][1][h] = fmaf(q1*k0, ak[0][1], acc[0][1][h]);
                acc[1][0][h] = fmaf(q0*k1, ak[1][0], acc[1][0][h]);
                acc[1][1][h] = fmaf(q1*k1, ak[1][1], acc[1][1][h]);
            }
        }
    }
    #pragma unroll
    for (int h = 0; h < NH; h++)
        #pragma unroll
        for (int jj = 0; jj < 2; jj++)
            #pragma unroll
            for (int ii = 0; ii < 2; ii++)
                attn[(((size_t)(b*NH + h) * NSEQ) + j0 + jl + jj) * NSEQ + i0 + il + ii] =
                    acc[jj][ii][h] * INV_T;
}

// ---------------- softmax over last axis, in place ---------------------------
__global__ __launch_bounds__(256)
void softmax_kernel(float* __restrict__ attn)
{
    size_t row = blockIdx.x;
    float* p = attn + row * NSEQ;
    int tid = threadIdx.x;
    __shared__ float redm[8];
    __shared__ float reds[8];

    float v0 = p[tid], v1 = p[tid + 256];
    float m = warp_max(fmaxf(v0, v1));
    if ((tid & 31) == 0) redm[tid >> 5] = m;
    __syncthreads();
    m = redm[0];
    #pragma unroll
    for (int w = 1; w < 8; w++) m = fmaxf(m, redm[w]);

    float e0 = __expf(v0 - m), e1 = __expf(v1 - m);
    float s = warp_sum(e0 + e1);
    if ((tid & 31) == 0) reds[tid >> 5] = s;
    __syncthreads();
    s = reds[0];
    #pragma unroll
    for (int w = 1; w < 8; w++) s += reds[w];

    float inv = 1.0f / s;
    p[tid]       = e0 * inv;
    p[tid + 256] = e1 * inv;
}

// ---------------- layer norm (one token per block) --------------------------
__global__ __launch_bounds__(256)
void layernorm_kernel(const float* __restrict__ x, const float* __restrict__ gam,
                      const float* __restrict__ bet, float* __restrict__ out)
{
    int t = blockIdx.x, tid = threadIdx.x;
    const float* xr = x + (size_t)t * DMODEL;
    __shared__ float red[8];

    float a0 = xr[tid], a1 = xr[tid + 256];
    float s = warp_sum(a0 + a1);
    if ((tid & 31) == 0) red[tid >> 5] = s;
    __syncthreads();
    s = red[0];
    #pragma unroll
    for (int w = 1; w < 8; w++) s += red[w];
    float mu = s * (1.0f / DMODEL);
    float d0 = a0 - mu, d1 = a1 - mu;
    __syncthreads();

    float q = warp_sum(d0*d0 + d1*d1);
    if ((tid & 31) == 0) red[tid >> 5] = q;
    __syncthreads();
    q = red[0];
    #pragma unroll
    for (int w = 1; w < 8; w++) q += red[w];
    float inv = rsqrtf(q * (1.0f / DMODEL) + LN_EPS);

    float* orow = out + (size_t)t * DMODEL;
    orow[tid]       = d0 * inv * gam[tid]       + bet[tid];
    orow[tid + 256] = d1 * inv * gam[tid + 256] + bet[tid + 256];
}

// ---------------- launch ----------------------------------------------------
extern "C" void kernel_launch(void* const* d_in, const int* in_sizes, int n_in,
                              void* d_out, int out_size)
{
    (void)in_sizes; (void)n_in; (void)out_size;
    const float* enc    = (const float*)d_in[0];
    const float* pos    = (const float*)d_in[1];
    const float* w_qs   = (const float*)d_in[2];
    const float* w_ks   = (const float*)d_in[3];
    const float* w_vs   = (const float*)d_in[4];
    const float* w_fc   = (const float*)d_in[5];
    const float* rp_w1  = (const float*)d_in[6];
    const float* rp_b1  = (const float*)d_in[7];
    const float* rp_w2  = (const float*)d_in[8];
    const float* rp_b2  = (const float*)d_in[9];
    const float* ln1_g  = (const float*)d_in[10];
    const float* ln1_b  = (const float*)d_in[11];
    const float* ln2_g  = (const float*)d_in[12];
    const float* ln2_b  = (const float*)d_in[13];
    const float* ffn_w1 = (const float*)d_in[14];
    const float* ffn_b1 = (const float*)d_in[15];
    const float* ffn_w2 = (const float*)d_in[16];
    const float* ffn_b2 = (const float*)d_in[17];

    float* out2 = (float*)d_out;                          // [4,512,512]
    float* attn = out2 + (size_t)TOK * DMODEL;            // [4,8,512,512]

    float *pv, *pheads, *ptmp1, *pln1, *pffh, *ptmp2;
    cudaGetSymbolAddress((void**)&pv,     g_v);
    cudaGetSymbolAddress((void**)&pheads, g_heads);
    cudaGetSymbolAddress((void**)&ptmp1,  g_tmp1);
    cudaGetSymbolAddress((void**)&pln1,   g_ln1);
    cudaGetSymbolAddress((void**)&pffh,   g_ffh);
    cudaGetSymbolAddress((void**)&ptmp2,  g_tmp2);

    // 1) collapse rel-pos MLP
    rp_combine_kernel<<<1, 64>>>(rp_w1, rp_b1, rp_w2, rp_b2);

    // 2) fused QKV projection (fp32, keeps attn output at fp32 accuracy)
    {
        dim3 g(1536/128, TOK/128, 1);  // (12,16)
        sgemm_qkv_kernel<<<g, 256>>>(enc, w_qs, w_ks, w_vs, DMODEL);
    }

    // 3) fused relative-position attention logits -> attn (pre-softmax, /T)
    {
        dim3 g(NSEQ/32, NSEQ/32, BB);
        scores_kernel<<<g, 256>>>(pos, attn);
    }

    // 4) softmax in place (normalized attn is part of the output)
    softmax_kernel<<<BB*NH*NSEQ, 256>>>(attn);

    // 5) AV (tf32): per (b,h): P[512,512] @ V[512,64] -> g_heads[b,n,h*64+dv]
    {
        dim3 g(1, NSEQ/128, BB*NH);    // (1,4,32)
        tgemm_kernel<64, 2, false, false, false, false><<<g, 256>>>(
            attn, pv, nullptr, nullptr, nullptr,
            DK, NSEQ, (size_t)NSEQ*NSEQ, (size_t)NSEQ*DK);
    }

    // 6) fc + residual(enc) -> g_tmp1 (tf32); LN1 -> g_ln1
    {
        dim3 g(DMODEL/128, TOK/128, 1); // (4,16)
        tgemm_kernel<128, 0, true, false, false, true><<<g, 256>>>(
            pheads, w_fc, nullptr, enc, ptmp1, DMODEL, DMODEL, 0, 0);
    }
    layernorm_kernel<<<TOK, 256>>>(ptmp1, ln1_g, ln1_b, pln1);

    // 7) FFN1 (tf32): relu(ln1 @ W1^T + b1) -> g_ffh
    {
        dim3 g(DINNER/128, TOK/128, 1); // (16,16)
        tgemm_kernel<128, 0, true, true, true, false><<<g, 256>>>(
            pln1, ffn_w1, ffn_b1, nullptr, pffh, DINNER, DMODEL, 0, 0);
    }

    // 8) FFN2 (tf32): ffh @ W2^T + b2 + ln1 -> g_tmp2
    {
        dim3 g(DMODEL/128, TOK/128, 1); // (4,16)
        tgemm_kernel<128, 0, true, true, false, true><<<g, 256>>>(
            pffh, ffn_w2, ffn_b2, pln1, ptmp2, DMODEL, DINNER, 0, 0);
    }

    // 9) LN2 -> out2
    layernorm_kernel<<<TOK, 256>>>(ptmp2, ln2_g, ln2_b, out2);
}

// round 9
// speedup vs baseline: 1.6880x; 1.0680x over previous
#include <cuda_runtime.h>
#include <math.h>
#include <stdint.h>

#define BB      4
#define NSEQ    512
#define DMODEL  512
#define NH      8
#define DK      64
#define TOK     (BB*NSEQ)      // 2048
#define DINNER  2048
#define LN_EPS  1e-6f
#define INV_T   0.125f         // 1/sqrt(64)

// ---------------- scratch ----------------------------------------------------
__device__ float g_q[BB*NH*NSEQ*DK];        // [b,h,n,d]
__device__ float g_k[BB*NH*NSEQ*DK];        // [b,h,n,d]
__device__ float g_v[BB*NH*NSEQ*DK];        // [b,h,n,d]
__device__ float g_Mmat[DK*4];              // combined rp matrix  M[d][p]
__device__ float g_cvec[DK];                // combined rp bias    c[d]
__device__ float g_heads[TOK*DMODEL];       // [b,n, h*dv]
__device__ float g_tmp1[TOK*DMODEL];
__device__ float g_ln1[TOK*DMODEL];
__device__ float g_ffh[TOK*DINNER];
__device__ float g_tmp2[TOK*DMODEL];

// ---------------- helpers ----------------------------------------------------
__device__ __forceinline__ float warp_sum(float v) {
    #pragma unroll
    for (int o = 16; o; o >>= 1) v += __shfl_xor_sync(0xffffffffu, v, o);
    return v;
}
__device__ __forceinline__ float warp_max(float v) {
    #pragma unroll
    for (int o = 16; o; o >>= 1) v = fmaxf(v, __shfl_xor_sync(0xffffffffu, v, o));
    return v;
}
__device__ __forceinline__ float to_tf32(float x) {
    uint32_t u;
    asm("cvt.rna.tf32.f32 %0, %1;" : "=r"(u) : "f"(x));
    return __uint_as_float(u);
}
__device__ __forceinline__ void mma_tf32(float (&c)[4], const uint32_t (&a)[4],
                                         const uint32_t (&b)[2]) {
    asm volatile(
        "mma.sync.aligned.m16n8k8.row.col.f32.tf32.tf32.f32 "
        "{%0,%1,%2,%3}, {%4,%5,%6,%7}, {%8,%9}, {%0,%1,%2,%3};\n"
        : "+f"(c[0]), "+f"(c[1]), "+f"(c[2]), "+f"(c[3])
        : "r"(a[0]), "r"(a[1]), "r"(a[2]), "r"(a[3]), "r"(b[0]), "r"(b[1]));
}

// ---------------- collapse rel-pos MLP: M = W2@W1, c = W2@b1 + b2 -----------
__global__ void rp_combine_kernel(const float* __restrict__ w1, const float* __restrict__ b1,
                                  const float* __restrict__ w2, const float* __restrict__ b2) {
    int d = threadIdx.x;
    if (d >= DK) return;
    float m0 = 0.f, m1 = 0.f, m2 = 0.f, m3 = 0.f, cc = 0.f;
    for (int k = 0; k < DK; k++) {
        float w = w2[d*DK + k];
        m0 = fmaf(w, w1[k*4+0], m0);
        m1 = fmaf(w, w1[k*4+1], m1);
        m2 = fmaf(w, w1[k*4+2], m2);
        m3 = fmaf(w, w1[k*4+3], m3);
        cc = fmaf(w, b1[k],      cc);
    }
    g_Mmat[d*4+0] = m0; g_Mmat[d*4+1] = m1;
    g_Mmat[d*4+2] = m2; g_Mmat[d*4+3] = m3;
    g_cvec[d] = cc + b2[d];
}

// ============================================================================
// QKV projection via 3xTF32 split MMA (fp32-grade accuracy on tensor cores).
// C = enc @ W^T for W in {w_qs, w_ks, w_vs} concatenated (N=1536);
// each launch covers 768 columns (colbase = 0 or 768).
// Tile 128x128, BK=8, 256 thr, 8 warps (2x4), m16n8k8 fragments.
// ============================================================================
__global__ __launch_bounds__(256)
void qkv3_kernel(const float* __restrict__ A,
                 const float* __restrict__ B0, const float* __restrict__ B1,
                 const float* __restrict__ B2, int colbase)
{
    const int K = DMODEL;
    __shared__ __align__(16) float Ah[2][8][136], Al[2][8][136];
    __shared__ __align__(16) float Bh[2][8][136], Bl[2][8][136];

    int tid  = threadIdx.x;
    int lane = tid & 31, warp = tid >> 5;
    int wm = warp >> 2, wn = warp & 3;
    int qr = lane >> 2, qc = lane & 3;
    int row0 = blockIdx.y << 7;
    int col0 = colbase + (blockIdx.x << 7);

    int wsel = col0 >> 9;
    const float* Bw = (wsel == 0) ? B0 : ((wsel == 1) ? B1 : B2);
    const float* Bb = Bw + (size_t)(col0 & 511) * K;

    int ar = tid >> 1, ak4 = (tid & 1) << 2;
    const float* Ald = A + (size_t)(row0 + ar) * K + ak4;
    const float* Bld = Bb + (size_t)ar * K + ak4;

    float acc[4][4][4];
    #pragma unroll
    for (int mt = 0; mt < 4; mt++)
        #pragma unroll
        for (int nt = 0; nt < 4; nt++)
            #pragma unroll
            for (int c = 0; c < 4; c++) acc[mt][nt][c] = 0.f;

    float4 av, bv;
    auto ldG = [&](int k0) {
        av = *(const float4*)(Ald + k0);
        bv = *(const float4*)(Bld + k0);
    };
    auto stS = [&](int buf) {
        const float* ap = (const float*)&av;
        const float* bp = (const float*)&bv;
        #pragma unroll
        for (int e = 0; e < 4; e++) {
            float x = ap[e], h = to_tf32(x);
            Ah[buf][ak4+e][ar] = h;
            Al[buf][ak4+e][ar] = to_tf32(x - h);
            float y = bp[e], g = to_tf32(y);
            Bh[buf][ak4+e][ar] = g;
            Bl[buf][ak4+e][ar] = to_tf32(y - g);
        }
    };
    auto compute = [&](int buf) {
        uint32_t afh[4][4], afl[4][4], bfh[4][2], bfl[4][2];
        #pragma unroll
        for (int mt = 0; mt < 4; mt++) {
            int mb = wm * 64 + mt * 16;
            afh[mt][0] = __float_as_uint(Ah[buf][qc  ][mb+qr  ]);
            afh[mt][1] = __float_as_uint(Ah[buf][qc  ][mb+qr+8]);
            afh[mt][2] = __float_as_uint(Ah[buf][qc+4][mb+qr  ]);
            afh[mt][3] = __float_as_uint(Ah[buf][qc+4][mb+qr+8]);
            afl[mt][0] = __float_as_uint(Al[buf][qc  ][mb+qr  ]);
            afl[mt][1] = __float_as_uint(Al[buf][qc  ][mb+qr+8]);
            afl[mt][2] = __float_as_uint(Al[buf][qc+4][mb+qr  ]);
            afl[mt][3] = __float_as_uint(Al[buf][qc+4][mb+qr+8]);
        }
        #pragma unroll
        for (int nt = 0; nt < 4; nt++) {
            int nb = wn * 32 + nt * 8;
            bfh[nt][0] = __float_as_uint(Bh[buf][qc  ][nb+qr]);
            bfh[nt][1] = __float_as_uint(Bh[buf][qc+4][nb+qr]);
            bfl[nt][0] = __float_as_uint(Bl[buf][qc  ][nb+qr]);
            bfl[nt][1] = __float_as_uint(Bl[buf][qc+4][nb+qr]);
        }
        #pragma unroll
        for (int mt = 0; mt < 4; mt++)
            #pragma unroll
            for (int nt = 0; nt < 4; nt++) {
                mma_tf32(acc[mt][nt], afh[mt], bfh[nt]);
                mma_tf32(acc[mt][nt], afh[mt], bfl[nt]);
                mma_tf32(acc[mt][nt], afl[mt], bfh[nt]);
            }
    };

    ldG(0);
    stS(0);
    __syncthreads();
    int buf = 0;
    for (int k0 = 8; k0 < K; k0 += 8) {
        ldG(k0);
        compute(buf);
        stS(buf ^ 1);
        __syncthreads();
        buf ^= 1;
    }
    compute(buf);

    // epilogue: split-head remap into g_q / g_k / g_v
    #pragma unroll
    for (int mt = 0; mt < 4; mt++) {
        int rbase = row0 + wm * 64 + mt * 16 + qr;
        #pragma unroll
        for (int nt = 0; nt < 4; nt++) {
            int c = col0 + wn * 32 + nt * 8 + 2 * qc;
            int ws = c >> 9, cc = c & 511;
            int h = cc >> 6, d = cc & 63;
            float* dst = (ws == 0) ? g_q : ((ws == 1) ? g_k : g_v);
            #pragma unroll
            for (int hh = 0; hh < 2; hh++) {
                int r = rbase + hh * 8;
                int b = r >> 9, n = r & 511;
                float2 v = make_float2(acc[mt][nt][2*hh], acc[mt][nt][2*hh+1]);
                *(float2*)(dst + ((((size_t)b * NH + h) * NSEQ) + n) * DK + d) = v;
            }
        }
    }
}

// ============================================================================
// TF32 tensor-core GEMM (AV, fc, FFN1, FFN2) — unchanged from round 8.
// ============================================================================
template<int TN, int MAP, bool BTRANS, bool BIAS, bool RELU, bool RESID>
__global__ __launch_bounds__(256)
void tgemm_kernel(const float* __restrict__ A, const float* __restrict__ B0,
                  const float* __restrict__ bias, const float* __restrict__ resid,
                  float* __restrict__ C, int N, int K,
                  size_t strideA, size_t strideB)
{
    constexpr int NT   = TN / 32;
    constexpr int WN   = TN / 4;
    constexpr int BPAD = (TN == 128) ? 136 : 72;

    __shared__ __align__(16) float As[2][16][136];
    __shared__ __align__(16) float Bs[2][16][BPAD];

    int tid  = threadIdx.x;
    int lane = tid & 31, warp = tid >> 5;
    int wm = warp >> 2, wn = warp & 3;
    int qr = lane >> 2, qc = lane & 3;
    int row0 = blockIdx.y << 7;
    int col0 = blockIdx.x * TN;
    int z    = blockIdx.z;

    const float* Ab = A + (size_t)z * strideA;
    const float* Bb = BTRANS ? (B0 + (size_t)col0 * K)
                             : (B0 + (size_t)z * strideB + col0);

    int ar = tid >> 2, ak = (tid & 3) << 2;
    const float* Ald = Ab + (size_t)(row0 + ar) * K + ak;
    const float* Bld_t = Bb + (size_t)ar * K + ak;
    int bkr = tid >> 4, bn4 = (tid & 15) << 2;
    const float* Bld_n = Bb + (size_t)bkr * N + bn4;

    float acc[4][NT][4];
    #pragma unroll
    for (int mt = 0; mt < 4; mt++)
        #pragma unroll
        for (int nt = 0; nt < NT; nt++)
            #pragma unroll
            for (int c = 0; c < 4; c++) acc[mt][nt][c] = 0.f;

    float4 av[2], bv[2];
    auto ldG = [&](int k0) {
        av[0] = *(const float4*)(Ald + k0);
        av[1] = *(const float4*)(Ald + (size_t)64 * K + k0);
        if (BTRANS) {
            bv[0] = *(const float4*)(Bld_t + k0);
            if (TN == 128) bv[1] = *(const float4*)(Bld_t + (size_t)64 * K + k0);
        } else {
            bv[0] = *(const float4*)(Bld_n + (size_t)k0 * N);
        }
    };
    auto stS = [&](int buf) {
        #pragma unroll
        for (int h = 0; h < 2; h++) {
            int r = ar + h * 64;
            As[buf][ak+0][r] = to_tf32(((const float*)&av[h])[0]);
            As[buf][ak+1][r] = to_tf32(((const float*)&av[h])[1]);
            As[buf][ak+2][r] = to_tf32(((const float*)&av[h])[2]);
            As[buf][ak+3][r] = to_tf32(((const float*)&av[h])[3]);
        }
        if (BTRANS) {
            #pragma unroll
            for (int h = 0; h < (TN == 128 ? 2 : 1); h++) {
                int r = ar + h * 64;
                if (TN == 128 || r < TN) {
                    Bs[buf][ak+0][r] = to_tf32(((const float*)&bv[h])[0]);
                    Bs[buf][ak+1][r] = to_tf32(((const float*)&bv[h])[1]);
                    Bs[buf][ak+2][r] = to_tf32(((const float*)&bv[h])[2]);
                    Bs[buf][ak+3][r] = to_tf32(((const float*)&bv[h])[3]);
                }
            }
        } else {
            float4 t = make_float4(to_tf32(bv[0].x), to_tf32(bv[0].y),
                                   to_tf32(bv[0].z), to_tf32(bv[0].w));
            *(float4*)&Bs[buf][bkr][bn4] = t;
        }
    };
    auto compute = [&](int buf) {
        #pragma unroll
        for (int ks = 0; ks < 2; ks++) {
            int kb = ks * 8;
            uint32_t af[4][4], bf[NT][2];
            #pragma unroll
            for (int mt = 0; mt < 4; mt++) {
                int mb = wm * 64 + mt * 16;
                af[mt][0] = __float_as_uint(As[buf][kb+qc  ][mb+qr  ]);
                af[mt][1] = __float_as_uint(As[buf][kb+qc  ][mb+qr+8]);
                af[mt][2] = __float_as_uint(As[buf][kb+qc+4][mb+qr  ]);
                af[mt][3] = __float_as_uint(As[buf][kb+qc+4][mb+qr+8]);
            }
            #pragma unroll
            for (int nt = 0; nt < NT; nt++) {
                int nb = wn * WN + nt * 8;
                bf[nt][0] = __float_as_uint(Bs[buf][kb+qc  ][nb+qr]);
                bf[nt][1] = __float_as_uint(Bs[buf][kb+qc+4][nb+qr]);
            }
            #pragma unroll
            for (int mt = 0; mt < 4; mt++)
                #pragma unroll
                for (int nt = 0; nt < NT; nt++)
                    mma_tf32(acc[mt][nt], af[mt], bf[nt]);
        }
    };

    ldG(0);
    stS(0);
    __syncthreads();
    int buf = 0;
    for (int k0 = 16; k0 < K; k0 += 16) {
        ldG(k0);
        compute(buf);
        stS(buf ^ 1);
        __syncthreads();
        buf ^= 1;
    }
    compute(buf);

    #pragma unroll
    for (int mt = 0; mt < 4; mt++) {
        int rbase = row0 + wm * 64 + mt * 16 + qr;
        #pragma unroll
        for (int nt = 0; nt < NT; nt++) {
            int cg = col0 + wn * WN + nt * 8 + 2 * qc;
            #pragma unroll
            for (int hh = 0; hh < 2; hh++) {
                int r = rbase + hh * 8;
                float2 v = make_float2(acc[mt][nt][2*hh], acc[mt][nt][2*hh+1]);
                if (BIAS) { v.x += bias[cg]; v.y += bias[cg+1]; }
                if (RESID) {
                    const float2 rz = *(const float2*)(resid + (size_t)r * N + cg);
                    v.x += rz.x; v.y += rz.y;
                }
                if (RELU) { v.x = fmaxf(v.x, 0.f); v.y = fmaxf(v.y, 0.f); }
                if (MAP == 0) {
                    *(float2*)(C + (size_t)r * N + cg) = v;
                } else {
                    int b = z >> 3, h2 = z & 7;
                    *(float2*)(g_heads + ((size_t)(b * NSEQ) + r) * DMODEL + h2 * DK + cg) = v;
                }
            }
        }
    }
}

// ============================================================================
// scores v2: d-major smem, float4 LDS over d, stride-16 point tiling.
// attn_raw[b,h,j,i] = (1/T)*sum_d q[b,h,i,d]*k[b,h,j,d]*(c[d]+pos[b,j,i,:]·M[d,:])
// Block: 32x32 (j,i) tile, all 8 heads; thread covers i in {tx,tx+16},
// j in {ty,ty+16}.
// ============================================================================
__global__ __launch_bounds__(256)
void scores_kernel(const float* __restrict__ pos, float* __restrict__ attn)
{
    __shared__ __align__(16) float Qs[256][20];  // [h*32 + i_local][d within chunk]
    __shared__ __align__(16) float Ks[256][20];
    __shared__ float4 M4[DK];
    __shared__ float  C4[DK];

    int tid = threadIdx.x;
    int b   = blockIdx.z;
    int i0  = blockIdx.x << 5, j0 = blockIdx.y << 5;
    int tx  = tid & 15, ty = tid >> 4;

    if (tid < DK) {
        M4[tid] = make_float4(g_Mmat[tid*4+0], g_Mmat[tid*4+1],
                              g_Mmat[tid*4+2], g_Mmat[tid*4+3]);
        C4[tid] = g_cvec[tid];
    }

    // pos for this thread's 4 (j,i) points: j = j0+ty+16jj, i = i0+tx+16ii
    float4 pr[2][2];
    #pragma unroll
    for (int jj = 0; jj < 2; jj++)
        #pragma unroll
        for (int ii = 0; ii < 2; ii++)
            pr[jj][ii] = *(const float4*)(pos +
                (((size_t)(b*NSEQ + j0 + ty + 16*jj) * NSEQ) + (i0 + tx + 16*ii)) * 4);

    float acc[2][2][NH];
    #pragma unroll
    for (int jj = 0; jj < 2; jj++)
        #pragma unroll
        for (int ii = 0; ii < 2; ii++)
            #pragma unroll
            for (int h = 0; h < NH; h++) acc[jj][ii][h] = 0.f;

    int fh = tid >> 5, fi = tid & 31;
    int base = fh * 32 + fi;
    const float* qb = g_q + (((size_t)(b*NH + fh) * NSEQ) + i0 + fi) * DK;
    const float* kb = g_k + (((size_t)(b*NH + fh) * NSEQ) + j0 + fi) * DK;

    for (int dc = 0; dc < DK; dc += 16) {
        __syncthreads();
        #pragma unroll
        for (int c4 = 0; c4 < 4; c4++) {
            *(float4*)&Qs[base][c4*4] = *(const float4*)(qb + dc + c4*4);
            *(float4*)&Ks[base][c4*4] = *(const float4*)(kb + dc + c4*4);
        }
        __syncthreads();

        #pragma unroll
        for (int g = 0; g < 4; g++) {
            int dbase = dc + g*4;
            float ak[4][2][2];
            #pragma unroll
            for (int dd = 0; dd < 4; dd++) {
                float4 m = M4[dbase + dd];
                float cc = C4[dbase + dd];
                #pragma unroll
                for (int jj = 0; jj < 2; jj++)
                    #pragma unroll
                    for (int ii = 0; ii < 2; ii++) {
                        float4 p = pr[jj][ii];
                        ak[dd][jj][ii] = fmaf(p.x, m.x, fmaf(p.y, m.y,
                                          fmaf(p.z, m.z, fmaf(p.w, m.w, cc))));
                    }
            }
            #pragma unroll
            for (int h = 0; h < NH; h++) {
                int o = h * 32;
                float4 q0 = *(const float4*)&Qs[o + tx     ][g*4];
                float4 q1 = *(const float4*)&Qs[o + tx + 16][g*4];
                float4 k0 = *(const float4*)&Ks[o + ty     ][g*4];
                float4 k1 = *(const float4*)&Ks[o + ty + 16][g*4];
                const float* qa = (const float*)&q0;
                const float* qc2 = (const float*)&q1;
                const float* ka = (const float*)&k0;
                const float* kc = (const float*)&k1;
                #pragma unroll
                for (int dd = 0; dd < 4; dd++) {
                    acc[0][0][h] = fmaf(qa[dd]*ka[dd],  ak[dd][0][0], acc[0][0][h]);
                    acc[0][1][h] = fmaf(qc2[dd]*ka[dd], ak[dd][0][1], acc[0][1][h]);
                    acc[1][0][h] = fmaf(qa[dd]*kc[dd],  ak[dd][1][0], acc[1][0][h]);
                    acc[1][1][h] = fmaf(qc2[dd]*kc[dd], ak[dd][1][1], acc[1][1][h]);
                }
            }
        }
    }

    #pragma unroll
    for (int h = 0; h < NH; h++)
        #pragma unroll
        for (int jj = 0; jj < 2; jj++)
            #pragma unroll
            for (int ii = 0; ii < 2; ii++)
                attn[(((size_t)(b*NH + h) * NSEQ) + j0 + ty + 16*jj) * NSEQ
                     + i0 + tx + 16*ii] = acc[jj][ii][h] * INV_T;
}

// ---------------- softmax over last axis, in place ---------------------------
__global__ __launch_bounds__(256)
void softmax_kernel(float* __restrict__ attn)
{
    size_t row = blockIdx.x;
    float* p = attn + row * NSEQ;
    int tid = threadIdx.x;
    __shared__ float redm[8];
    __shared__ float reds[8];

    float v0 = p[tid], v1 = p[tid + 256];
    float m = warp_max(fmaxf(v0, v1));
    if ((tid & 31) == 0) redm[tid >> 5] = m;
    __syncthreads();
    m = redm[0];
    #pragma unroll
    for (int w = 1; w < 8; w++) m = fmaxf(m, redm[w]);

    float e0 = __expf(v0 - m), e1 = __expf(v1 - m);
    float s = warp_sum(e0 + e1);
    if ((tid & 31) == 0) reds[tid >> 5] = s;
    __syncthreads();
    s = reds[0];
    #pragma unroll
    for (int w = 1; w < 8; w++) s += reds[w];

    float inv = 1.0f / s;
    p[tid]       = e0 * inv;
    p[tid + 256] = e1 * inv;
}

// ---------------- layer norm (one token per block) ---------------------------
__global__ __launch_bounds__(256)
void layernorm_kernel(const float* __restrict__ x, const float* __restrict__ gam,
                      const float* __restrict__ bet, float* __restrict__ out)
{
    int t = blockIdx.x, tid = threadIdx.x;
    const float* xr = x + (size_t)t * DMODEL;
    __shared__ float red[8];

    float a0 = xr[tid], a1 = xr[tid + 256];
    float s = warp_sum(a0 + a1);
    if ((tid & 31) == 0) red[tid >> 5] = s;
    __syncthreads();
    s = red[0];
    #pragma unroll
    for (int w = 1; w < 8; w++) s += red[w];
    float mu = s * (1.0f / DMODEL);
    float d0 = a0 - mu, d1 = a1 - mu;
    __syncthreads();

    float q = warp_sum(d0*d0 + d1*d1);
    if ((tid & 31) == 0) red[tid >> 5] = q;
    __syncthreads();
    q = red[0];
    #pragma unroll
    for (int w = 1; w < 8; w++) q += red[w];
    float inv = rsqrtf(q * (1.0f / DMODEL) + LN_EPS);

    float* orow = out + (size_t)t * DMODEL;
    orow[tid]       = d0 * inv * gam[tid]       + bet[tid];
    orow[tid + 256] = d1 * inv * gam[tid + 256] + bet[tid + 256];
}

// ---------------- launch -----------------------------------------------------
extern "C" void kernel_launch(void* const* d_in, const int* in_sizes, int n_in,
                              void* d_out, int out_size)
{
    (void)in_sizes; (void)n_in; (void)out_size;
    const float* enc    = (const float*)d_in[0];
    const float* pos    = (const float*)d_in[1];
    const float* w_qs   = (const float*)d_in[2];
    const float* w_ks   = (const float*)d_in[3];
    const float* w_vs   = (const float*)d_in[4];
    const float* w_fc   = (const float*)d_in[5];
    const float* rp_w1  = (const float*)d_in[6];
    const float* rp_b1  = (const float*)d_in[7];
    const float* rp_w2  = (const float*)d_in[8];
    const float* rp_b2  = (const float*)d_in[9];
    const float* ln1_g  = (const float*)d_in[10];
    const float* ln1_b  = (const float*)d_in[11];
    const float* ln2_g  = (const float*)d_in[12];
    const float* ln2_b  = (const float*)d_in[13];
    const float* ffn_w1 = (const float*)d_in[14];
    const float* ffn_b1 = (const float*)d_in[15];
    const float* ffn_w2 = (const float*)d_in[16];
    const float* ffn_b2 = (const float*)d_in[17];

    float* out2 = (float*)d_out;                          // [4,512,512]
    float* attn = out2 + (size_t)TOK * DMODEL;            // [4,8,512,512]

    float *pv, *pheads, *ptmp1, *pln1, *pffh, *ptmp2;
    cudaGetSymbolAddress((void**)&pv,     g_v);
    cudaGetSymbolAddress((void**)&pheads, g_heads);
    cudaGetSymbolAddress((void**)&ptmp1,  g_tmp1);
    cudaGetSymbolAddress((void**)&pln1,   g_ln1);
    cudaGetSymbolAddress((void**)&pffh,   g_ffh);
    cudaGetSymbolAddress((void**)&ptmp2,  g_tmp2);

    // 1) collapse rel-pos MLP
    rp_combine_kernel<<<1, 64>>>(rp_w1, rp_b1, rp_w2, rp_b2);

    // 2+3) QKV projection, 3xTF32 split, two column halves
    {
        dim3 g(6, TOK/128, 1);   // 96 CTAs each
        qkv3_kernel<<<g, 256>>>(enc, w_qs, w_ks, w_vs, 0);
        qkv3_kernel<<<g, 256>>>(enc, w_qs, w_ks, w_vs, 768);
    }

    // 4) fused relative-position attention logits  (launch slot #4 -> profiled)
    {
        dim3 g(NSEQ/32, NSEQ/32, BB);
        scores_kernel<<<g, 256>>>(pos, attn);
    }

    // 5) softmax in place
    softmax_kernel<<<BB*NH*NSEQ, 256>>>(attn);

    // 6) AV (tf32): per (b,h): P[512,512] @ V[512,64] -> g_heads
    {
        dim3 g(1, NSEQ/128, BB*NH);
        tgemm_kernel<64, 2, false, false, false, false><<<g, 256>>>(
            attn, pv, nullptr, nullptr, nullptr,
            DK, NSEQ, (size_t)NSEQ*NSEQ, (size_t)NSEQ*DK);
    }

    // 7) fc + residual(enc) -> g_tmp1 (tf32, TN=64 for 128 CTAs); LN1
    {
        dim3 g(DMODEL/64, TOK/128, 1);  // (8,16) = 128 CTAs
        tgemm_kernel<64, 0, true, false, false, true><<<g, 256>>>(
            pheads, w_fc, nullptr, enc, ptmp1, DMODEL, DMODEL, 0, 0);
    }
    layernorm_kernel<<<TOK, 256>>>(ptmp1, ln1_g, ln1_b, pln1);

    // 8) FFN1 (tf32): relu(ln1 @ W1^T + b1) -> g_ffh
    {
        dim3 g(DINNER/128, TOK/128, 1); // 256 CTAs
        tgemm_kernel<128, 0, true, true, true, false><<<g, 256>>>(
            pln1, ffn_w1, ffn_b1, nullptr, pffh, DINNER, DMODEL, 0, 0);
    }

    // 9) FFN2 (tf32): ffh @ W2^T + b2 + ln1 -> g_tmp2 (TN=64 for 128 CTAs)
    {
        dim3 g(DMODEL/64, TOK/128, 1);  // 128 CTAs
        tgemm_kernel<64, 0, true, true, false, true><<<g, 256>>>(
            pffh, ffn_w2, ffn_b2, pln1, ptmp2, DMODEL, DINNER, 0, 0);
    }

    // 10) LN2 -> out2
    layernorm_kernel<<<TOK, 256>>>(ptmp2, ln2_g, ln2_b, out2);
}

// round 10
// speedup vs baseline: 1.6885x; 1.0003x over previous
#include <cuda_runtime.h>
#include <math.h>
#include <stdint.h>

#define BB      4
#define NSEQ    512
#define DMODEL  512
#define NH      8
#define DK      64
#define TOK     (BB*NSEQ)      // 2048
#define DINNER  2048
#define LN_EPS  1e-6f
#define INV_T   0.125f         // 1/sqrt(64)

// ---------------- scratch ----------------------------------------------------
__device__ float g_q[BB*NH*NSEQ*DK];        // [b,h,n,d]
__device__ float g_k[BB*NH*NSEQ*DK];        // [b,h,n,d]
__device__ float g_v[BB*NH*NSEQ*DK];        // [b,h,n,d]
__device__ float g_Mmat[DK*4];              // combined rp matrix  M[d][p]
__device__ float g_cvec[DK];                // combined rp bias    c[d]
__device__ float g_heads[TOK*DMODEL];       // [b,n, h*dv]
__device__ float g_tmp1[TOK*DMODEL];
__device__ float g_ln1[TOK*DMODEL];
__device__ float g_ffh[TOK*DINNER];
__device__ float g_tmp2[TOK*DMODEL];

// ---------------- helpers ----------------------------------------------------
__device__ __forceinline__ float warp_sum(float v) {
    #pragma unroll
    for (int o = 16; o; o >>= 1) v += __shfl_xor_sync(0xffffffffu, v, o);
    return v;
}
__device__ __forceinline__ float warp_max(float v) {
    #pragma unroll
    for (int o = 16; o; o >>= 1) v = fmaxf(v, __shfl_xor_sync(0xffffffffu, v, o));
    return v;
}
__device__ __forceinline__ float to_tf32(float x) {
    uint32_t u;
    asm("cvt.rna.tf32.f32 %0, %1;" : "=r"(u) : "f"(x));
    return __uint_as_float(u);
}
__device__ __forceinline__ void mma_tf32(float (&c)[4], const uint32_t (&a)[4],
                                         const uint32_t (&b)[2]) {
    asm volatile(
        "mma.sync.aligned.m16n8k8.row.col.f32.tf32.tf32.f32 "
        "{%0,%1,%2,%3}, {%4,%5,%6,%7}, {%8,%9}, {%0,%1,%2,%3};\n"
        : "+f"(c[0]), "+f"(c[1]), "+f"(c[2]), "+f"(c[3])
        : "r"(a[0]), "r"(a[1]), "r"(a[2]), "r"(a[3]), "r"(b[0]), "r"(b[1]));
}

// ---------------- collapse rel-pos MLP: M = W2@W1, c = W2@b1 + b2 -----------
__global__ void rp_combine_kernel(const float* __restrict__ w1, const float* __restrict__ b1,
                                  const float* __restrict__ w2, const float* __restrict__ b2) {
    int d = threadIdx.x;
    if (d >= DK) return;
    float m0 = 0.f, m1 = 0.f, m2 = 0.f, m3 = 0.f, cc = 0.f;
    for (int k = 0; k < DK; k++) {
        float w = w2[d*DK + k];
        m0 = fmaf(w, w1[k*4+0], m0);
        m1 = fmaf(w, w1[k*4+1], m1);
        m2 = fmaf(w, w1[k*4+2], m2);
        m3 = fmaf(w, w1[k*4+3], m3);
        cc = fmaf(w, b1[k],      cc);
    }
    g_Mmat[d*4+0] = m0; g_Mmat[d*4+1] = m1;
    g_Mmat[d*4+2] = m2; g_Mmat[d*4+3] = m3;
    g_cvec[d] = cc + b2[d];
}

// ============================================================================
// QKV projection via 3xTF32 split MMA (fp32-grade accuracy on tensor cores).
// C = enc @ W^T for W in {w_qs, w_ks, w_vs} concatenated (N=1536);
// each launch covers 768 columns (colbase = 0 or 768).
// Tile 128x128, BK=8, 256 thr, 8 warps (2x4), m16n8k8 fragments.
// ============================================================================
__global__ __launch_bounds__(256)
void qkv3_kernel(const float* __restrict__ A,
                 const float* __restrict__ B0, const float* __restrict__ B1,
                 const float* __restrict__ B2, int colbase)
{
    const int K = DMODEL;
    __shared__ __align__(16) float Ah[2][8][136], Al[2][8][136];
    __shared__ __align__(16) float Bh[2][8][136], Bl[2][8][136];

    int tid  = threadIdx.x;
    int lane = tid & 31, warp = tid >> 5;
    int wm = warp >> 2, wn = warp & 3;
    int qr = lane >> 2, qc = lane & 3;
    int row0 = blockIdx.y << 7;
    int col0 = colbase + (blockIdx.x << 7);

    int wsel = col0 >> 9;
    const float* Bw = (wsel == 0) ? B0 : ((wsel == 1) ? B1 : B2);
    const float* Bb = Bw + (size_t)(col0 & 511) * K;

    int ar = tid >> 1, ak4 = (tid & 1) << 2;
    const float* Ald = A + (size_t)(row0 + ar) * K + ak4;
    const float* Bld = Bb + (size_t)ar * K + ak4;

    float acc[4][4][4];
    #pragma unroll
    for (int mt = 0; mt < 4; mt++)
        #pragma unroll
        for (int nt = 0; nt < 4; nt++)
            #pragma unroll
            for (int c = 0; c < 4; c++) acc[mt][nt][c] = 0.f;

    float4 av, bv;
    auto ldG = [&](int k0) {
        av = *(const float4*)(Ald + k0);
        bv = *(const float4*)(Bld + k0);
    };
    auto stS = [&](int buf) {
        const float* ap = (const float*)&av;
        const float* bp = (const float*)&bv;
        #pragma unroll
        for (int e = 0; e < 4; e++) {
            float x = ap[e], h = to_tf32(x);
            Ah[buf][ak4+e][ar] = h;
            Al[buf][ak4+e][ar] = to_tf32(x - h);
            float y = bp[e], g = to_tf32(y);
            Bh[buf][ak4+e][ar] = g;
            Bl[buf][ak4+e][ar] = to_tf32(y - g);
        }
    };
    auto compute = [&](int buf) {
        uint32_t afh[4][4], afl[4][4], bfh[4][2], bfl[4][2];
        #pragma unroll
        for (int mt = 0; mt < 4; mt++) {
            int mb = wm * 64 + mt * 16;
            afh[mt][0] = __float_as_uint(Ah[buf][qc  ][mb+qr  ]);
            afh[mt][1] = __float_as_uint(Ah[buf][qc  ][mb+qr+8]);
            afh[mt][2] = __float_as_uint(Ah[buf][qc+4][mb+qr  ]);
            afh[mt][3] = __float_as_uint(Ah[buf][qc+4][mb+qr+8]);
            afl[mt][0] = __float_as_uint(Al[buf][qc  ][mb+qr  ]);
            afl[mt][1] = __float_as_uint(Al[buf][qc  ][mb+qr+8]);
            afl[mt][2] = __float_as_uint(Al[buf][qc+4][mb+qr  ]);
            afl[mt][3] = __float_as_uint(Al[buf][qc+4][mb+qr+8]);
        }
        #pragma unroll
        for (int nt = 0; nt < 4; nt++) {
            int nb = wn * 32 + nt * 8;
            bfh[nt][0] = __float_as_uint(Bh[buf][qc  ][nb+qr]);
            bfh[nt][1] = __float_as_uint(Bh[buf][qc+4][nb+qr]);
            bfl[nt][0] = __float_as_uint(Bl[buf][qc  ][nb+qr]);
            bfl[nt][1] = __float_as_uint(Bl[buf][qc+4][nb+qr]);
        }
        #pragma unroll
        for (int mt = 0; mt < 4; mt++)
            #pragma unroll
            for (int nt = 0; nt < 4; nt++) {
                mma_tf32(acc[mt][nt], afh[mt], bfh[nt]);
                mma_tf32(acc[mt][nt], afh[mt], bfl[nt]);
                mma_tf32(acc[mt][nt], afl[mt], bfh[nt]);
            }
    };

    ldG(0);
    stS(0);
    __syncthreads();
    int buf = 0;
    for (int k0 = 8; k0 < K; k0 += 8) {
        ldG(k0);
        compute(buf);
        stS(buf ^ 1);
        __syncthreads();
        buf ^= 1;
    }
    compute(buf);

    // epilogue: split-head remap into g_q / g_k / g_v
    #pragma unroll
    for (int mt = 0; mt < 4; mt++) {
        int rbase = row0 + wm * 64 + mt * 16 + qr;
        #pragma unroll
        for (int nt = 0; nt < 4; nt++) {
            int c = col0 + wn * 32 + nt * 8 + 2 * qc;
            int ws = c >> 9, cc = c & 511;
            int h = cc >> 6, d = cc & 63;
            float* dst = (ws == 0) ? g_q : ((ws == 1) ? g_k : g_v);
            #pragma unroll
            for (int hh = 0; hh < 2; hh++) {
                int r = rbase + hh * 8;
                int b = r >> 9, n = r & 511;
                float2 v = make_float2(acc[mt][nt][2*hh], acc[mt][nt][2*hh+1]);
                *(float2*)(dst + ((((size_t)b * NH + h) * NSEQ) + n) * DK + d) = v;
            }
        }
    }
}

// ============================================================================
// TF32 tensor-core GEMM (AV, fc, FFN1, FFN2) — unchanged from round 8.
// ============================================================================
template<int TN, int MAP, bool BTRANS, bool BIAS, bool RELU, bool RESID>
__global__ __launch_bounds__(256)
void tgemm_kernel(const float* __restrict__ A, const float* __restrict__ B0,
                  const float* __restrict__ bias, const float* __restrict__ resid,
                  float* __restrict__ C, int N, int K,
                  size_t strideA, size_t strideB)
{
    constexpr int NT   = TN / 32;
    constexpr int WN   = TN / 4;
    constexpr int BPAD = (TN == 128) ? 136 : 72;

    __shared__ __align__(16) float As[2][16][136];
    __shared__ __align__(16) float Bs[2][16][BPAD];

    int tid  = threadIdx.x;
    int lane = tid & 31, warp = tid >> 5;
    int wm = warp >> 2, wn = warp & 3;
    int qr = lane >> 2, qc = lane & 3;
    int row0 = blockIdx.y << 7;
    int col0 = blockIdx.x * TN;
    int z    = blockIdx.z;

    const float* Ab = A + (size_t)z * strideA;
    const float* Bb = BTRANS ? (B0 + (size_t)col0 * K)
                             : (B0 + (size_t)z * strideB + col0);

    int ar = tid >> 2, ak = (tid & 3) << 2;
    const float* Ald = Ab + (size_t)(row0 + ar) * K + ak;
    const float* Bld_t = Bb + (size_t)ar * K + ak;
    int bkr = tid >> 4, bn4 = (tid & 15) << 2;
    const float* Bld_n = Bb + (size_t)bkr * N + bn4;

    float acc[4][NT][4];
    #pragma unroll
    for (int mt = 0; mt < 4; mt++)
        #pragma unroll
        for (int nt = 0; nt < NT; nt++)
            #pragma unroll
            for (int c = 0; c < 4; c++) acc[mt][nt][c] = 0.f;

    float4 av[2], bv[2];
    auto ldG = [&](int k0) {
        av[0] = *(const float4*)(Ald + k0);
        av[1] = *(const float4*)(Ald + (size_t)64 * K + k0);
        if (BTRANS) {
            bv[0] = *(const float4*)(Bld_t + k0);
            if (TN == 128) bv[1] = *(const float4*)(Bld_t + (size_t)64 * K + k0);
        } else {
            bv[0] = *(const float4*)(Bld_n + (size_t)k0 * N);
        }
    };
    auto stS = [&](int buf) {
        #pragma unroll
        for (int h = 0; h < 2; h++) {
            int r = ar + h * 64;
            As[buf][ak+0][r] = to_tf32(((const float*)&av[h])[0]);
            As[buf][ak+1][r] = to_tf32(((const float*)&av[h])[1]);
            As[buf][ak+2][r] = to_tf32(((const float*)&av[h])[2]);
            As[buf][ak+3][r] = to_tf32(((const float*)&av[h])[3]);
        }
        if (BTRANS) {
            #pragma unroll
            for (int h = 0; h < (TN == 128 ? 2 : 1); h++) {
                int r = ar + h * 64;
                if (TN == 128 || r < TN) {
                    Bs[buf][ak+0][r] = to_tf32(((const float*)&bv[h])[0]);
                    Bs[buf][ak+1][r] = to_tf32(((const float*)&bv[h])[1]);
                    Bs[buf][ak+2][r] = to_tf32(((const float*)&bv[h])[2]);
                    Bs[buf][ak+3][r] = to_tf32(((const float*)&bv[h])[3]);
                }
            }
        } else {
            float4 t = make_float4(to_tf32(bv[0].x), to_tf32(bv[0].y),
                                   to_tf32(bv[0].z), to_tf32(bv[0].w));
            *(float4*)&Bs[buf][bkr][bn4] = t;
        }
    };
    auto compute = [&](int buf) {
        #pragma unroll
        for (int ks = 0; ks < 2; ks++) {
            int kb = ks * 8;
            uint32_t af[4][4], bf[NT][2];
            #pragma unroll
            for (int mt = 0; mt < 4; mt++) {
                int mb = wm * 64 + mt * 16;
                af[mt][0] = __float_as_uint(As[buf][kb+qc  ][mb+qr  ]);
                af[mt][1] = __float_as_uint(As[buf][kb+qc  ][mb+qr+8]);
                af[mt][2] = __float_as_uint(As[buf][kb+qc+4][mb+qr  ]);
                af[mt][3] = __float_as_uint(As[buf][kb+qc+4][mb+qr+8]);
            }
            #pragma unroll
            for (int nt = 0; nt < NT; nt++) {
                int nb = wn * WN + nt * 8;
                bf[nt][0] = __float_as_uint(Bs[buf][kb+qc  ][nb+qr]);
                bf[nt][1] = __float_as_uint(Bs[buf][kb+qc+4][nb+qr]);
            }
            #pragma unroll
            for (int mt = 0; mt < 4; mt++)
                #pragma unroll
                for (int nt = 0; nt < NT; nt++)
                    mma_tf32(acc[mt][nt], af[mt], bf[nt]);
        }
    };

    ldG(0);
    stS(0);
    __syncthreads();
    int buf = 0;
    for (int k0 = 16; k0 < K; k0 += 16) {
        ldG(k0);
        compute(buf);
        stS(buf ^ 1);
        __syncthreads();
        buf ^= 1;
    }
    compute(buf);

    #pragma unroll
    for (int mt = 0; mt < 4; mt++) {
        int rbase = row0 + wm * 64 + mt * 16 + qr;
        #pragma unroll
        for (int nt = 0; nt < NT; nt++) {
            int cg = col0 + wn * WN + nt * 8 + 2 * qc;
            #pragma unroll
            for (int hh = 0; hh < 2; hh++) {
                int r = rbase + hh * 8;
                float2 v = make_float2(acc[mt][nt][2*hh], acc[mt][nt][2*hh+1]);
                if (BIAS) { v.x += bias[cg]; v.y += bias[cg+1]; }
                if (RESID) {
                    const float2 rz = *(const float2*)(resid + (size_t)r * N + cg);
                    v.x += rz.x; v.y += rz.y;
                }
                if (RELU) { v.x = fmaxf(v.x, 0.f); v.y = fmaxf(v.y, 0.f); }
                if (MAP == 0) {
                    *(float2*)(C + (size_t)r * N + cg) = v;
                } else {
                    int b = z >> 3, h2 = z & 7;
                    *(float2*)(g_heads + ((size_t)(b * NSEQ) + r) * DMODEL + h2 * DK + cg) = v;
                }
            }
        }
    }
}

// ============================================================================
// scores v2: d-major smem, float4 LDS over d, stride-16 point tiling.
// attn_raw[b,h,j,i] = (1/T)*sum_d q[b,h,i,d]*k[b,h,j,d]*(c[d]+pos[b,j,i,:]·M[d,:])
// Block: 32x32 (j,i) tile, all 8 heads; thread covers i in {tx,tx+16},
// j in {ty,ty+16}.
// ============================================================================
__global__ __launch_bounds__(256)
void scores_kernel(const float* __restrict__ pos, float* __restrict__ attn)
{
    __shared__ __align__(16) float Qs[256][20];  // [h*32 + i_local][d within chunk]
    __shared__ __align__(16) float Ks[256][20];
    __shared__ float4 M4[DK];
    __shared__ float  C4[DK];

    int tid = threadIdx.x;
    int b   = blockIdx.z;
    int i0  = blockIdx.x << 5, j0 = blockIdx.y << 5;
    int tx  = tid & 15, ty = tid >> 4;

    if (tid < DK) {
        M4[tid] = make_float4(g_Mmat[tid*4+0], g_Mmat[tid*4+1],
                              g_Mmat[tid*4+2], g_Mmat[tid*4+3]);
        C4[tid] = g_cvec[tid];
    }

    // pos for this thread's 4 (j,i) points: j = j0+ty+16jj, i = i0+tx+16ii
    float4 pr[2][2];
    #pragma unroll
    for (int jj = 0; jj < 2; jj++)
        #pragma unroll
        for (int ii = 0; ii < 2; ii++)
            pr[jj][ii] = *(const float4*)(pos +
                (((size_t)(b*NSEQ + j0 + ty + 16*jj) * NSEQ) + (i0 + tx + 16*ii)) * 4);

    float acc[2][2][NH];
    #pragma unroll
    for (int jj = 0; jj < 2; jj++)
        #pragma unroll
        for (int ii = 0; ii < 2; ii++)
            #pragma unroll
            for (int h = 0; h < NH; h++) acc[jj][ii][h] = 0.f;

    int fh = tid >> 5, fi = tid & 31;
    int base = fh * 32 + fi;
    const float* qb = g_q + (((size_t)(b*NH + fh) * NSEQ) + i0 + fi) * DK;
    const float* kb = g_k + (((size_t)(b*NH + fh) * NSEQ) + j0 + fi) * DK;

    for (int dc = 0; dc < DK; dc += 16) {
        __syncthreads();
        #pragma unroll
        for (int c4 = 0; c4 < 4; c4++) {
            *(float4*)&Qs[base][c4*4] = *(const float4*)(qb + dc + c4*4);
            *(float4*)&Ks[base][c4*4] = *(const float4*)(kb + dc + c4*4);
        }
        __syncthreads();

        #pragma unroll
        for (int g = 0; g < 4; g++) {
            int dbase = dc + g*4;
            float ak[4][2][2];
            #pragma unroll
            for (int dd = 0; dd < 4; dd++) {
                float4 m = M4[dbase + dd];
                float cc = C4[dbase + dd];
                #pragma unroll
                for (int jj = 0; jj < 2; jj++)
                    #pragma unroll
                    for (int ii = 0; ii < 2; ii++) {
                        float4 p = pr[jj][ii];
                        ak[dd][jj][ii] = fmaf(p.x, m.x, fmaf(p.y, m.y,
                                          fmaf(p.z, m.z, fmaf(p.w, m.w, cc))));
                    }
            }
            #pragma unroll
            for (int h = 0; h < NH; h++) {
                int o = h * 32;
                float4 q0 = *(const float4*)&Qs[o + tx     ][g*4];
                float4 q1 = *(const float4*)&Qs[o + tx + 16][g*4];
                float4 k0 = *(const float4*)&Ks[o + ty     ][g*4];
                float4 k1 = *(const float4*)&Ks[o + ty + 16][g*4];
                const float* qa = (const float*)&q0;
                const float* qc2 = (const float*)&q1;
                const float* ka = (const float*)&k0;
                const float* kc = (const float*)&k1;
                #pragma unroll
                for (int dd = 0; dd < 4; dd++) {
                    acc[0][0][h] = fmaf(qa[dd]*ka[dd],  ak[dd][0][0], acc[0][0][h]);
                    acc[0][1][h] = fmaf(qc2[dd]*ka[dd], ak[dd][0][1], acc[0][1][h]);
                    acc[1][0][h] = fmaf(qa[dd]*kc[dd],  ak[dd][1][0], acc[1][0][h]);
                    acc[1][1][h] = fmaf(qc2[dd]*kc[dd], ak[dd][1][1], acc[1][1][h]);
                }
            }
        }
    }

    #pragma unroll
    for (int h = 0; h < NH; h++)
        #pragma unroll
        for (int jj = 0; jj < 2; jj++)
            #pragma unroll
            for (int ii = 0; ii < 2; ii++)
                attn[(((size_t)(b*NH + h) * NSEQ) + j0 + ty + 16*jj) * NSEQ
                     + i0 + tx + 16*ii] = acc[jj][ii][h] * INV_T;
}

// ---------------- softmax over last axis, in place ---------------------------
__global__ __launch_bounds__(256)
void softmax_kernel(float* __restrict__ attn)
{
    size_t row = blockIdx.x;
    float* p = attn + row * NSEQ;
    int tid = threadIdx.x;
    __shared__ float redm[8];
    __shared__ float reds[8];

    float v0 = p[tid], v1 = p[tid + 256];
    float m = warp_max(fmaxf(v0, v1));
    if ((tid & 31) == 0) redm[tid >> 5] = m;
    __syncthreads();
    m = redm[0];
    #pragma unroll
    for (int w = 1; w < 8; w++) m = fmaxf(m, redm[w]);

    float e0 = __expf(v0 - m), e1 = __expf(v1 - m);
    float s = warp_sum(e0 + e1);
    if ((tid & 31) == 0) reds[tid >> 5] = s;
    __syncthreads();
    s = reds[0];
    #pragma unroll
    for (int w = 1; w < 8; w++) s += reds[w];

    float inv = 1.0f / s;
    p[tid]       = e0 * inv;
    p[tid + 256] = e1 * inv;
}

// ---------------- layer norm (one token per block) ---------------------------
__global__ __launch_bounds__(256)
void layernorm_kernel(const float* __restrict__ x, const float* __restrict__ gam,
                      const float* __restrict__ bet, float* __restrict__ out)
{
    int t = blockIdx.x, tid = threadIdx.x;
    const float* xr = x + (size_t)t * DMODEL;
    __shared__ float red[8];

    float a0 = xr[tid], a1 = xr[tid + 256];
    float s = warp_sum(a0 + a1);
    if ((tid & 31) == 0) red[tid >> 5] = s;
    __syncthreads();
    s = red[0];
    #pragma unroll
    for (int w = 1; w < 8; w++) s += red[w];
    float mu = s * (1.0f / DMODEL);
    float d0 = a0 - mu, d1 = a1 - mu;
    __syncthreads();

    float q = warp_sum(d0*d0 + d1*d1);
    if ((tid & 31) == 0) red[tid >> 5] = q;
    __syncthreads();
    q = red[0];
    #pragma unroll
    for (int w = 1; w < 8; w++) q += red[w];
    float inv = rsqrtf(q * (1.0f / DMODEL) + LN_EPS);

    float* orow = out + (size_t)t * DMODEL;
    orow[tid]       = d0 * inv * gam[tid]       + bet[tid];
    orow[tid + 256] = d1 * inv * gam[tid + 256] + bet[tid + 256];
}

// ---------------- launch -----------------------------------------------------
extern "C" void kernel_launch(void* const* d_in, const int* in_sizes, int n_in,
                              void* d_out, int out_size)
{
    (void)in_sizes; (void)n_in; (void)out_size;
    const float* enc    = (const float*)d_in[0];
    const float* pos    = (const float*)d_in[1];
    const float* w_qs   = (const float*)d_in[2];
    const float* w_ks   = (const float*)d_in[3];
    const float* w_vs   = (const float*)d_in[4];
    const float* w_fc   = (const float*)d_in[5];
    const float* rp_w1  = (const float*)d_in[6];
    const float* rp_b1  = (const float*)d_in[7];
    const float* rp_w2  = (const float*)d_in[8];
    const float* rp_b2  = (const float*)d_in[9];
    const float* ln1_g  = (const float*)d_in[10];
    const float* ln1_b  = (const float*)d_in[11];
    const float* ln2_g  = (const float*)d_in[12];
    const float* ln2_b  = (const float*)d_in[13];
    const float* ffn_w1 = (const float*)d_in[14];
    const float* ffn_b1 = (const float*)d_in[15];
    const float* ffn_w2 = (const float*)d_in[16];
    const float* ffn_b2 = (const float*)d_in[17];

    float* out2 = (float*)d_out;                          // [4,512,512]
    float* attn = out2 + (size_t)TOK * DMODEL;            // [4,8,512,512]

    float *pv, *pheads, *ptmp1, *pln1, *pffh, *ptmp2;
    cudaGetSymbolAddress((void**)&pv,     g_v);
    cudaGetSymbolAddress((void**)&pheads, g_heads);
    cudaGetSymbolAddress((void**)&ptmp1,  g_tmp1);
    cudaGetSymbolAddress((void**)&pln1,   g_ln1);
    cudaGetSymbolAddress((void**)&pffh,   g_ffh);
    cudaGetSymbolAddress((void**)&ptmp2,  g_tmp2);

    // 1) collapse rel-pos MLP
    rp_combine_kernel<<<1, 64>>>(rp_w1, rp_b1, rp_w2, rp_b2);

    // 2+3) QKV projection, 3xTF32 split, two column halves
    {
        dim3 g(6, TOK/128, 1);   // 96 CTAs each
        qkv3_kernel<<<g, 256>>>(enc, w_qs, w_ks, w_vs, 0);
        qkv3_kernel<<<g, 256>>>(enc, w_qs, w_ks, w_vs, 768);
    }

    // 4) fused relative-position attention logits  (launch slot #4 -> profiled)
    {
        dim3 g(NSEQ/32, NSEQ/32, BB);
        scores_kernel<<<g, 256>>>(pos, attn);
    }

    // 5) softmax in place
    softmax_kernel<<<BB*NH*NSEQ, 256>>>(attn);

    // 6) AV (tf32): per (b,h): P[512,512] @ V[512,64] -> g_heads
    {
        dim3 g(1, NSEQ/128, BB*NH);
        tgemm_kernel<64, 2, false, false, false, false><<<g, 256>>>(
            attn, pv, nullptr, nullptr, nullptr,
            DK, NSEQ, (size_t)NSEQ*NSEQ, (size_t)NSEQ*DK);
    }

    // 7) fc + residual(enc) -> g_tmp1 (tf32, TN=64 for 128 CTAs); LN1
    {
        dim3 g(DMODEL/64, TOK/128, 1);  // (8,16) = 128 CTAs
        tgemm_kernel<64, 0, true, false, false, true><<<g, 256>>>(
            pheads, w_fc, nullptr, enc, ptmp1, DMODEL, DMODEL, 0, 0);
    }
    layernorm_kernel<<<TOK, 256>>>(ptmp1, ln1_g, ln1_b, pln1);

    // 8) FFN1 (tf32): relu(ln1 @ W1^T + b1) -> g_ffh
    {
        dim3 g(DINNER/128, TOK/128, 1); // 256 CTAs
        tgemm_kernel<128, 0, true, true, true, false><<<g, 256>>>(
            pln1, ffn_w1, ffn_b1, nullptr, pffh, DINNER, DMODEL, 0, 0);
    }

    // 9) FFN2 (tf32): ffh @ W2^T + b2 + ln1 -> g_tmp2 (TN=64 for 128 CTAs)
    {
        dim3 g(DMODEL/64, TOK/128, 1);  // 128 CTAs
        tgemm_kernel<64, 0, true, true, false, true><<<g, 256>>>(
            pffh, ffn_w2, ffn_b2, pln1, ptmp2, DMODEL, DINNER, 0, 0);
    }

    // 10) LN2 -> out2
    layernorm_kernel<<<TOK, 256>>>(ptmp2, ln2_g, ln2_b, out2);
}